// round 11
// baseline (speedup 1.0000x reference)
#include <cuda_runtime.h>
#include <cuda_bf16.h>
#include <cstdint>

#define BB 4
#define SS 2048
#define HH 1024
#define LL 4
#define FF 4096
#define NN (BB*SS)
#define NCHUNK 32
#define CLEN (SS/NCHUNK)

// GEMM tiling: BM=128, BN=128, BK=64, 256 thr (2x4 warps, 64x32 warp tile), 3 stages, 2 CTA/SM
#define PITCH 144                     // 128B data + 16B pad per 64-bf16 row
#define A_BYTES (128*PITCH)           // 18432
#define STG_BYTES (2*A_BYTES)         // 36864 (A + B)
#define NSTAGE 3
#define SMEM_SZ (NSTAGE*STG_BYTES)    // 110592

// ---------------- scratch ----------------
__device__ __align__(256) float g_h  [(size_t)NN*HH];
__device__ __align__(256) float g_tre[(size_t)NN*HH];
__device__ __align__(256) float g_tim[(size_t)NN*HH];
__device__ __align__(256) float g_y  [(size_t)NN*HH];
__device__ float2 g_carry[BB*NCHUNK*HH];
__device__ __align__(256) __nv_bfloat16 g_hs[(size_t)NN*2*HH];   // h split [hi|lo]
__device__ __align__(256) __nv_bfloat16 g_sp[(size_t)NN*4*HH];   // scan out [re_hi|re_lo|im_hi|im_lo]
__device__ __align__(256) __nv_bfloat16 g_fs[(size_t)NN*2*FF];   // gelu out [hi|lo]
__device__ __align__(256) __nv_bfloat16 g_wbu[(size_t)LL*2048*2048];
__device__ __align__(256) __nv_bfloat16 g_wy [(size_t)LL*1024*4096];
__device__ __align__(256) __nv_bfloat16 g_wf1[(size_t)LL*4096*2048];
__device__ __align__(256) __nv_bfloat16 g_wf2[(size_t)LL*1024*8192];

// ---------------- helpers ----------------
__device__ __forceinline__ uint32_t smem_u32(const void* p){
    uint32_t a;
    asm("{ .reg .u64 t; cvta.to.shared.u64 t, %1; cvt.u32.u64 %0, t; }" : "=r"(a) : "l"(p));
    return a;
}
#define CPA_COMMIT() asm volatile("cp.async.commit_group;" ::: "memory")
#define CPA_WAIT1()  asm volatile("cp.async.wait_group 1;" ::: "memory")
__device__ __forceinline__ void cpa16(uint32_t d, const void* s){
    asm volatile("cp.async.cg.shared.global [%0], [%1], 16;" :: "r"(d), "l"(s));
}
__device__ __forceinline__ void ldsm4(uint32_t& r0, uint32_t& r1, uint32_t& r2, uint32_t& r3, uint32_t a){
    asm volatile("ldmatrix.sync.aligned.m8n8.x4.shared.b16 {%0,%1,%2,%3}, [%4];"
        : "=r"(r0), "=r"(r1), "=r"(r2), "=r"(r3) : "r"(a));
}
__device__ __forceinline__ void mma16816(float* d, const uint32_t* a, const uint32_t* b){
    asm volatile("mma.sync.aligned.m16n8k16.row.col.f32.bf16.bf16.f32 "
        "{%0,%1,%2,%3}, {%4,%5,%6,%7}, {%8,%9}, {%0,%1,%2,%3};"
        : "+f"(d[0]), "+f"(d[1]), "+f"(d[2]), "+f"(d[3])
        : "r"(a[0]), "r"(a[1]), "r"(a[2]), "r"(a[3]), "r"(b[0]), "r"(b[1]));
}
__device__ __forceinline__ void split2(float x, __nv_bfloat16& hi, __nv_bfloat16& lo){
    hi = __float2bfloat16(x);
    lo = __float2bfloat16(x - __bfloat162float(hi));
}
__device__ __forceinline__ void split4_store(float4 v, __nv_bfloat16* bhi, __nv_bfloat16* blo){
    float xs[4] = {v.x, v.y, v.z, v.w};
    uint32_t h[4], l[4];
    #pragma unroll
    for (int i = 0; i < 4; i++){
        __nv_bfloat16 hb, lb; split2(xs[i], hb, lb);
        h[i] = (uint32_t)__bfloat16_as_ushort(hb);
        l[i] = (uint32_t)__bfloat16_as_ushort(lb);
    }
    *(uint2*)bhi = make_uint2(h[0] | (h[1]<<16), h[2] | (h[3]<<16));
    *(uint2*)blo = make_uint2(l[0] | (l[1]<<16), l[2] | (l[3]<<16));
}

// ---------------- embedding (+ split) ----------------
__global__ void embed_kernel(const int* __restrict__ ids, const float* __restrict__ we,
                             const float* __restrict__ pe, float* __restrict__ out,
                             __nv_bfloat16* __restrict__ outs)
{
    int e = blockIdx.x * blockDim.x + threadIdx.x;
    int n  = e >> 8;
    int hq = (e & 255) << 2;
    int s  = n & (SS - 1);
    int id = ids[n];
    float4 w = *(const float4*)(we + (size_t)id * HH + hq);
    float4 p = *(const float4*)(pe + (size_t)s  * HH + hq);
    float4 v = make_float4(w.x+p.x, w.y+p.y, w.z+p.z, w.w+p.w);
    *(float4*)(out + (size_t)n * HH + hq) = v;
    split4_store(v, outs + (size_t)n*2*HH + hq, outs + (size_t)n*2*HH + HH + hq);
}

// ---------------- weight splitter (vectorized x4) ----------------
__global__ void split_w4(const float* __restrict__ W, __nv_bfloat16* __restrict__ out,
                         int ksh, long ldo, long coff, float sgn, int total4)
{
    int i = blockIdx.x * blockDim.x + threadIdx.x;
    if (i >= total4) return;
    long e = (long)i * 4;
    long K = 1L << ksh;
    long r = e >> ksh;
    long c = e & (K - 1);
    float4 x = *(const float4*)(W + e);
    x.x *= sgn; x.y *= sgn; x.z *= sgn; x.w *= sgn;
    split4_store(x, out + r*ldo + coff + c, out + r*ldo + coff + K + c);
}

// ---------------- mma.sync GEMM: C[8192 rows x M cols] = A'[.,K'] @ B'[M,K']^T ----------------
struct GArgs {
    const __nv_bfloat16* A; const __nv_bfloat16* B;
    long lda, ldb;
    int k1sh, nst, mode;        // mode 0=BU(gamma) 1=Y 2=F1(gelu+split) 3=F2(bias)
    int amap[6], bmap[6];
    const float* vec;
    float* out0; float* out1;
    __nv_bfloat16* osplit;
};

__global__ __launch_bounds__(256, 2) void mma_gemm(const __grid_constant__ GArgs g)
{
    extern __shared__ char sm[];
    __shared__ float tab[128];
    const uint32_t sbase = smem_u32(sm);
    const int tid = threadIdx.x, lane = tid & 31, wid = tid >> 5;
    const int n0 = blockIdx.y * 128;     // token rows
    const int m0 = blockIdx.x * 128;     // output cols

    if (tid < 128){
        if (g.mode == 0)
            tab[tid] = sqrtf(fmaxf(1.f - expf(-2.f * expf(g.vec[(m0 + tid) & (HH-1)])), 0.f));
        else if (g.mode >= 2)
            tab[tid] = g.vec[m0 + tid];
    }

    // cp.async mapping: thread -> row tid>>1, 64B half (tid&1), 4 chunks of 16B per tile
    const int arow = tid >> 1;
    const int ac0  = (tid & 1) * 4;               // chunk group (0 or 4)
    const __nv_bfloat16* gA = g.A + (size_t)(n0 + arow) * g.lda + ac0*8;
    const __nv_bfloat16* gB = g.B + (size_t)(m0 + arow) * g.ldb + ac0*8;
    const uint32_t dA = (uint32_t)(arow*PITCH + ac0*16);
    const uint32_t dB = (uint32_t)(A_BYTES + arow*PITCH + ac0*16);

    const int k1m = (1 << g.k1sh) - 1;
    auto load_stage = [&](int s, uint32_t base){
        int k0 = s << 6;                          // BK=64 elements
        int seg = k0 >> g.k1sh;
        long ka = ((long)g.amap[seg] << g.k1sh) + (k0 & k1m);
        long kb = ((long)g.bmap[seg] << g.k1sh) + (k0 & k1m);
        const __nv_bfloat16* pa = gA + ka;
        const __nv_bfloat16* pb = gB + kb;
        uint32_t da = base + dA, db = base + dB;
        cpa16(da,      pa);      cpa16(da + 16, pa + 8);
        cpa16(da + 32, pa + 16); cpa16(da + 48, pa + 24);
        cpa16(db,      pb);      cpa16(db + 16, pb + 8);
        cpa16(db + 32, pb + 16); cpa16(db + 48, pb + 24);
        CPA_COMMIT();
    };

    // warp layout: 2 (M) x 4 (N); warp tile 64x32
    const int warp_m = wid & 1, warp_n = wid >> 1;
    const int ra = (lane & 7) + (((lane >> 3) & 1) << 3);
    const int ca = (lane >> 4) * 16;
    const int rb = (lane & 7) + (((lane >> 4) & 1) << 3);
    const int cb = ((lane >> 3) & 1) * 16;
    uint32_t aoff[4], boff[2];
    #pragma unroll
    for (int mt = 0; mt < 4; mt++)
        aoff[mt] = (uint32_t)((warp_m*64 + mt*16 + ra) * PITCH + ca);
    #pragma unroll
    for (int ntp = 0; ntp < 2; ntp++)
        boff[ntp] = (uint32_t)(A_BYTES + (warp_n*32 + ntp*16 + rb) * PITCH + cb);

    float acc[4][4][4];
    #pragma unroll
    for (int i = 0; i < 4; i++)
        #pragma unroll
        for (int j = 0; j < 4; j++)
            #pragma unroll
            for (int r = 0; r < 4; r++) acc[i][j][r] = 0.f;

    load_stage(0, sbase);
    load_stage(1, sbase + STG_BYTES);

    const int nst = g.nst;
    int buf = 0, lbuf = 2;
    for (int i = 0; i < nst; i++){
        CPA_WAIT1();
        __syncthreads();
        uint32_t sb0 = sbase + (uint32_t)buf * STG_BYTES;
        #pragma unroll
        for (int s = 0; s < 4; s++){             // four k16 steps per stage
            uint32_t a[4][4], b[4][2];
            #pragma unroll
            for (int mt = 0; mt < 4; mt++)
                ldsm4(a[mt][0], a[mt][1], a[mt][2], a[mt][3], sb0 + aoff[mt] + s*32);
            #pragma unroll
            for (int ntp = 0; ntp < 2; ntp++){
                uint32_t r0, r1, r2, r3;
                ldsm4(r0, r1, r2, r3, sb0 + boff[ntp] + s*32);
                b[2*ntp][0] = r0;   b[2*ntp][1] = r1;
                b[2*ntp+1][0] = r2; b[2*ntp+1][1] = r3;
            }
            #pragma unroll
            for (int mt = 0; mt < 4; mt++)
                #pragma unroll
                for (int nt = 0; nt < 4; nt++)
                    mma16816(acc[mt][nt], a[mt], b[nt]);
        }
        int j = i + NSTAGE - 1;
        if (j < nst) load_stage(j, sbase + (uint32_t)lbuf * STG_BYTES);
        else CPA_COMMIT();
        if (++buf == NSTAGE) buf = 0;
        if (++lbuf == NSTAGE) lbuf = 0;
    }

    // epilogue
    const int rbase = n0 + warp_m*64 + (lane >> 2);
    const int cbase = warp_n*32 + (lane & 3)*2;
    #pragma unroll
    for (int mt = 0; mt < 4; mt++){
        #pragma unroll
        for (int nt = 0; nt < 4; nt++){
            int cl = cbase + nt*8;
            int col = m0 + cl;
            #pragma unroll
            for (int h = 0; h < 2; h++){
                int row = rbase + mt*16 + h*8;
                float v0 = acc[mt][nt][h*2+0];
                float v1 = acc[mt][nt][h*2+1];
                if (g.mode == 0){
                    float* dst = (col < HH) ? g.out0 : g.out1;
                    int cm = col & (HH-1);
                    *(float2*)(dst + (size_t)row*HH + cm) =
                        make_float2(v0 * tab[cl], v1 * tab[cl+1]);
                } else if (g.mode == 1){
                    *(float2*)(g.out0 + (size_t)row*HH + col) = make_float2(v0, v1);
                } else if (g.mode == 2){
                    float x0 = v0 + tab[cl], x1 = v1 + tab[cl+1];
                    x0 = x0 * normcdff(x0);                 // exact GELU
                    x1 = x1 * normcdff(x1);
                    __nv_bfloat16 h0, l0, h1, l1;
                    split2(x0, h0, l0); split2(x1, h1, l1);
                    uint32_t hw = (uint32_t)__bfloat16_as_ushort(h0) | ((uint32_t)__bfloat16_as_ushort(h1) << 16);
                    uint32_t lw = (uint32_t)__bfloat16_as_ushort(l0) | ((uint32_t)__bfloat16_as_ushort(l1) << 16);
                    size_t bh = (size_t)row * (2*FF) + col;
                    *(uint32_t*)(g.osplit + bh)      = hw;
                    *(uint32_t*)(g.osplit + bh + FF) = lw;
                } else {
                    *(float2*)(g.out0 + (size_t)row*HH + col) =
                        make_float2(v0 + tab[cl], v1 + tab[cl+1]);
                }
            }
        }
    }
}

// ---------------- chunked complex scan ----------------
__device__ __forceinline__ void lam_of(const float* nul, const float* thl, int u,
                                       float& lre, float& lim)
{
    float r   = expf(-expf(nul[u]));
    float ang = expf(thl[u]);
    lre = r * cosf(ang);
    lim = r * sinf(ang);
}

// pass1: per-chunk final state only (no writeback)
__global__ void scan_pass1(const float* __restrict__ nul, const float* __restrict__ thl,
                           const float* __restrict__ tre, const float* __restrict__ tim,
                           float2* __restrict__ carry)
{
    int t = blockIdx.x * blockDim.x + threadIdx.x;
    int u = t & (HH - 1);
    int rest = t >> 10;
    int c = rest & (NCHUNK - 1);
    int b = rest >> 5;
    float lre, lim; lam_of(nul, thl, u, lre, lim);
    size_t base = ((size_t)b * SS + (size_t)c * CLEN) * HH + u;
    float sre = 0.f, sim = 0.f;
    #pragma unroll 4
    for (int i = 0; i < CLEN; i++) {
        size_t ix = base + (size_t)i * HH;
        float xr = tre[ix], xi = tim[ix];
        float nr = fmaf(lre, sre, fmaf(-lim, sim, xr));
        float ni = fmaf(lre, sim, fmaf( lim, sre, xi));
        sre = nr; sim = ni;
    }
    carry[(b * NCHUNK + c) * HH + u] = make_float2(sre, sim);
}

__global__ void scan_pass2(const float* __restrict__ nul, const float* __restrict__ thl,
                           float2* __restrict__ carry)
{
    int t = blockIdx.x * blockDim.x + threadIdx.x;
    int u = t & (HH - 1);
    int b = t >> 10;
    float lre, lim; lam_of(nul, thl, u, lre, lim);
    float pr = 1.f, pi = 0.f;
    #pragma unroll
    for (int i = 0; i < CLEN; i++) {
        float nr = pr * lre - pi * lim;
        float ni = pr * lim + pi * lre;
        pr = nr; pi = ni;
    }
    float cre = 0.f, cim = 0.f;
    for (int c = 0; c < NCHUNK; c++) {
        int ix = (b * NCHUNK + c) * HH + u;
        float2 f = carry[ix];
        carry[ix] = make_float2(cre, cim);
        float nr = fmaf(pr, cre, fmaf(-pi, cim, f.x));
        float ni = fmaf(pr, cim, fmaf( pi, cre, f.y));
        cre = nr; cim = ni;
    }
}

// pass3: redo local scan from exclusive carry, emit bf16 splits
__global__ void scan_pass3(const float* __restrict__ nul, const float* __restrict__ thl,
                           const float* __restrict__ tre, const float* __restrict__ tim,
                           const float2* __restrict__ carry, __nv_bfloat16* __restrict__ sp)
{
    int t = blockIdx.x * blockDim.x + threadIdx.x;
    int u = t & (HH - 1);
    int rest = t >> 10;
    int c = rest & (NCHUNK - 1);
    int b = rest >> 5;
    float2 cc = carry[(b * NCHUNK + c) * HH + u];
    float lre, lim; lam_of(nul, thl, u, lre, lim);
    size_t base = ((size_t)b * SS + (size_t)c * CLEN) * HH + u;
    size_t nbase = (size_t)b * SS + (size_t)c * CLEN;
    float sre = cc.x, sim = cc.y;
    for (int i = 0; i < CLEN; i++) {
        size_t ix = base + (size_t)i * HH;
        float xr = tre[ix], xi = tim[ix];
        float nr = fmaf(lre, sre, fmaf(-lim, sim, xr));
        float ni = fmaf(lre, sim, fmaf( lim, sre, xi));
        sre = nr; sim = ni;
        size_t ro = (nbase + i) * (4*HH) + u;
        __nv_bfloat16 h1, l1, h2, l2;
        split2(sre, h1, l1); split2(sim, h2, l2);
        sp[ro]        = h1;
        sp[ro + HH]   = l1;
        sp[ro + 2*HH] = h2;
        sp[ro + 3*HH] = l2;
    }
}

// ---------------- fused residual + RMS-LN (+ split output) ----------------
__global__ void ln_kernel(const float* __restrict__ h, const float* __restrict__ y,
                          const float* __restrict__ Dl, const float* __restrict__ bias,
                          float* __restrict__ out, __nv_bfloat16* __restrict__ osplit)
{
    int n = blockIdx.x;
    int t = threadIdx.x;
    size_t idx = (size_t)n * HH + (t << 2);
    float4 hv = *(const float4*)(h + idx);
    float4 yv = *(const float4*)(y + idx);
    float4 z;
    if (Dl) {
        float4 dv = *(const float4*)(Dl + (t << 2));
        z.x = fmaf(hv.x, 1.f + dv.x, yv.x);
        z.y = fmaf(hv.y, 1.f + dv.y, yv.y);
        z.z = fmaf(hv.z, 1.f + dv.z, yv.z);
        z.w = fmaf(hv.w, 1.f + dv.w, yv.w);
    } else {
        z.x = hv.x + yv.x; z.y = hv.y + yv.y; z.z = hv.z + yv.z; z.w = hv.w + yv.w;
    }
    float s = z.x*z.x + z.y*z.y + z.z*z.z + z.w*z.w;
    #pragma unroll
    for (int o = 16; o; o >>= 1) s += __shfl_xor_sync(0xffffffffu, s, o);
    __shared__ float red[8];
    if ((t & 31) == 0) red[t >> 5] = s;
    __syncthreads();
    float tot = red[0]+red[1]+red[2]+red[3]+red[4]+red[5]+red[6]+red[7];
    float inv = rsqrtf(tot * (1.f / (float)HH) + 1e-12f);
    float4 bv = *(const float4*)(bias + (t << 2));
    float4 o4 = make_float4(fmaf(z.x, inv, bv.x), fmaf(z.y, inv, bv.y),
                            fmaf(z.z, inv, bv.z), fmaf(z.w, inv, bv.w));
    *(float4*)(out + idx) = o4;
    split4_store(o4, osplit + (size_t)n*2*HH + (t<<2),
                     osplit + (size_t)n*2*HH + HH + (t<<2));
}

// ---------------- launch ----------------
extern "C" void kernel_launch(void* const* d_in, const int* in_sizes, int n_in,
                              void* d_out, int out_size)
{
    const int*   ids = (const int*)  d_in[0];
    const float* we  = (const float*)d_in[1];
    const float* pe  = (const float*)d_in[2];
    const float* nu  = (const float*)d_in[3];
    const float* th  = (const float*)d_in[4];
    const float* Bre = (const float*)d_in[5];
    const float* Bim = (const float*)d_in[6];
    const float* Cre = (const float*)d_in[7];
    const float* Cim = (const float*)d_in[8];
    const float* Dp  = (const float*)d_in[9];
    const float* rnb = (const float*)d_in[10];
    const float* w1  = (const float*)d_in[11];
    const float* b1  = (const float*)d_in[12];
    const float* w2  = (const float*)d_in[13];
    const float* b2  = (const float*)d_in[14];
    const float* fnb = (const float*)d_in[15];
    float* out = (float*)d_out;

    float *ph, *ptre, *ptim, *py; float2* pc;
    __nv_bfloat16 *phs, *psp, *pfs, *pwbu, *pwy, *pwf1, *pwf2;
    cudaGetSymbolAddress((void**)&ph,   g_h);
    cudaGetSymbolAddress((void**)&ptre, g_tre);
    cudaGetSymbolAddress((void**)&ptim, g_tim);
    cudaGetSymbolAddress((void**)&py,   g_y);
    cudaGetSymbolAddress((void**)&pc,   g_carry);
    cudaGetSymbolAddress((void**)&phs,  g_hs);
    cudaGetSymbolAddress((void**)&psp,  g_sp);
    cudaGetSymbolAddress((void**)&pfs,  g_fs);
    cudaGetSymbolAddress((void**)&pwbu, g_wbu);
    cudaGetSymbolAddress((void**)&pwy,  g_wy);
    cudaGetSymbolAddress((void**)&pwf1, g_wf1);
    cudaGetSymbolAddress((void**)&pwf2, g_wf2);

    cudaFuncSetAttribute(mma_gemm, cudaFuncAttributeMaxDynamicSharedMemorySize, SMEM_SZ);

    // weight splits (hi|lo) bf16, vectorized x4
    for (int l = 0; l < LL; l++) {
        size_t hh = (size_t)HH*HH;
        split_w4<<<HH*HH/4/256, 256>>>(Bre + l*hh, pwbu + (size_t)l*2048*2048,              10, 2048, 0,    1.f, HH*HH/4);
        split_w4<<<HH*HH/4/256, 256>>>(Bim + l*hh, pwbu + (size_t)l*2048*2048 + 1024L*2048, 10, 2048, 0,    1.f, HH*HH/4);
        split_w4<<<HH*HH/4/256, 256>>>(Cre + l*hh, pwy  + (size_t)l*1024*4096,              10, 4096, 0,    1.f, HH*HH/4);
        split_w4<<<HH*HH/4/256, 256>>>(Cim + l*hh, pwy  + (size_t)l*1024*4096,              10, 4096, 2048,-1.f, HH*HH/4);
        split_w4<<<FF*HH/4/256, 256>>>(w1 + (size_t)l*FF*HH, pwf1 + (size_t)l*4096*2048,    10, 2048, 0,    1.f, FF*HH/4);
        split_w4<<<FF*HH/4/256, 256>>>(w2 + (size_t)l*HH*FF, pwf2 + (size_t)l*1024*8192,    12, 8192, 0,    1.f, HH*FF/4);
    }

    embed_kernel<<<(size_t)NN*HH/4/256, 256>>>(ids, we, pe, ph, phs);

    int am1[6] = {0,0,1,0,0,0}, bm1[6] = {0,1,0,0,0,0};          // 3-seg: hihi, hilo, lohi
    int am2[6] = {0,0,1,2,2,3}, bm2[6] = {0,1,0,2,3,2};          // 6-seg complex

    for (int l = 0; l < LL; l++) {
        const float* nul = nu + l*HH;
        const float* thl = th + l*HH;

        // BU: [h_hi|h_lo] x [Bre;Bim] -> tre/tim (gamma fused). M=2048, K'=3072
        GArgs a = {};
        a.A = phs; a.B = pwbu + (size_t)l*2048*2048;
        a.lda = 2048; a.ldb = 2048;
        a.k1sh = 10; a.nst = 48; a.mode = 0;
        for (int i = 0; i < 6; i++){ a.amap[i] = am1[i]; a.bmap[i] = bm1[i]; }
        a.vec = nul; a.out0 = ptre; a.out1 = ptim;
        mma_gemm<<<dim3(16, 64), 256, SMEM_SZ>>>(a);

        scan_pass1<<<BB*NCHUNK*HH/256, 256>>>(nul, thl, ptre, ptim, pc);
        scan_pass2<<<BB*HH/256, 256>>>(nul, thl, pc);
        scan_pass3<<<BB*NCHUNK*HH/256, 256>>>(nul, thl, ptre, ptim, pc, psp);

        // Y: [re_hi|re_lo|im_hi|im_lo] x [Cre|-Cim] -> y. M=1024, K'=6144
        a = GArgs{};
        a.A = psp; a.B = pwy + (size_t)l*1024*4096;
        a.lda = 4096; a.ldb = 4096;
        a.k1sh = 10; a.nst = 96; a.mode = 1;
        for (int i = 0; i < 6; i++){ a.amap[i] = am2[i]; a.bmap[i] = bm2[i]; }
        a.out0 = py;
        mma_gemm<<<dim3(8, 64), 256, SMEM_SZ>>>(a);

        ln_kernel<<<NN, 256>>>(ph, py, Dp + l*HH, rnb + l*HH, ph, phs);

        // FFN1: h_split x w1_split -> gelu -> g_fs. M=4096, K'=3072
        a = GArgs{};
        a.A = phs; a.B = pwf1 + (size_t)l*4096*2048;
        a.lda = 2048; a.ldb = 2048;
        a.k1sh = 10; a.nst = 48; a.mode = 2;
        for (int i = 0; i < 6; i++){ a.amap[i] = am1[i]; a.bmap[i] = bm1[i]; }
        a.vec = b1 + l*FF; a.osplit = pfs;
        mma_gemm<<<dim3(32, 64), 256, SMEM_SZ>>>(a);

        // FFN2: g_fs x w2_split + bias -> y. M=1024, K'=12288
        a = GArgs{};
        a.A = pfs; a.B = pwf2 + (size_t)l*1024*8192;
        a.lda = 8192; a.ldb = 8192;
        a.k1sh = 12; a.nst = 192; a.mode = 3;
        for (int i = 0; i < 6; i++){ a.amap[i] = am1[i]; a.bmap[i] = bm1[i]; }
        a.vec = b2 + l*HH; a.out0 = py;
        mma_gemm<<<dim3(8, 64), 256, SMEM_SZ>>>(a);

        float* lnout = (l == LL-1) ? out : ph;
        ln_kernel<<<NN, 256>>>(ph, py, nullptr, fnb + l*HH, lnout, phs);
    }
}

// round 12
// speedup vs baseline: 1.0786x; 1.0786x over previous
#include <cuda_runtime.h>
#include <cuda_bf16.h>
#include <cstdint>

#define BB 4
#define SS 2048
#define HH 1024
#define LL 4
#define FF 4096
#define NN (BB*SS)
#define NCHUNK 32
#define CLEN (SS/NCHUNK)

// GEMM tiling (R10 shape, deeper pipe): BM=128, BN=128, BK=32, 256 thr (2x4 warps), 5 stages
#define PITCH 80                      // 64B data + 16B pad per 32-bf16 row
#define A_BYTES (128*PITCH)           // 10240
#define STG_BYTES (2*A_BYTES)         // 20480 (A + B)
#define NSTAGE 5
#define SMEM_SZ (NSTAGE*STG_BYTES)    // 102400

// ---------------- scratch ----------------
__device__ __align__(256) float g_h  [(size_t)NN*HH];
__device__ __align__(256) float g_tre[(size_t)NN*HH];
__device__ __align__(256) float g_tim[(size_t)NN*HH];
__device__ __align__(256) float g_y  [(size_t)NN*HH];
__device__ float2 g_carry[BB*NCHUNK*HH];
__device__ __align__(256) __nv_bfloat16 g_hs[(size_t)NN*2*HH];   // h split [hi|lo]
__device__ __align__(256) __nv_bfloat16 g_sp[(size_t)NN*4*HH];   // scan out [re_hi|re_lo|im_hi|im_lo]
__device__ __align__(256) __nv_bfloat16 g_fs[(size_t)NN*2*FF];   // gelu out [hi|lo]
__device__ __align__(256) __nv_bfloat16 g_wbu[(size_t)LL*2048*2048];
__device__ __align__(256) __nv_bfloat16 g_wy [(size_t)LL*1024*4096];
__device__ __align__(256) __nv_bfloat16 g_wf1[(size_t)LL*4096*2048];
__device__ __align__(256) __nv_bfloat16 g_wf2[(size_t)LL*1024*8192];

// ---------------- helpers ----------------
__device__ __forceinline__ uint32_t smem_u32(const void* p){
    uint32_t a;
    asm("{ .reg .u64 t; cvta.to.shared.u64 t, %1; cvt.u32.u64 %0, t; }" : "=r"(a) : "l"(p));
    return a;
}
#define CPA_COMMIT() asm volatile("cp.async.commit_group;" ::: "memory")
#define CPA_WAIT3()  asm volatile("cp.async.wait_group 3;" ::: "memory")
__device__ __forceinline__ void cpa16(uint32_t d, const void* s){
    asm volatile("cp.async.cg.shared.global [%0], [%1], 16;" :: "r"(d), "l"(s));
}
__device__ __forceinline__ void ldsm4(uint32_t& r0, uint32_t& r1, uint32_t& r2, uint32_t& r3, uint32_t a){
    asm volatile("ldmatrix.sync.aligned.m8n8.x4.shared.b16 {%0,%1,%2,%3}, [%4];"
        : "=r"(r0), "=r"(r1), "=r"(r2), "=r"(r3) : "r"(a));
}
__device__ __forceinline__ void mma16816(float* d, const uint32_t* a, const uint32_t* b){
    asm volatile("mma.sync.aligned.m16n8k16.row.col.f32.bf16.bf16.f32 "
        "{%0,%1,%2,%3}, {%4,%5,%6,%7}, {%8,%9}, {%0,%1,%2,%3};"
        : "+f"(d[0]), "+f"(d[1]), "+f"(d[2]), "+f"(d[3])
        : "r"(a[0]), "r"(a[1]), "r"(a[2]), "r"(a[3]), "r"(b[0]), "r"(b[1]));
}
__device__ __forceinline__ void split2(float x, __nv_bfloat16& hi, __nv_bfloat16& lo){
    hi = __float2bfloat16(x);
    lo = __float2bfloat16(x - __bfloat162float(hi));
}
__device__ __forceinline__ void split4_store(float4 v, __nv_bfloat16* bhi, __nv_bfloat16* blo){
    float xs[4] = {v.x, v.y, v.z, v.w};
    uint32_t h[4], l[4];
    #pragma unroll
    for (int i = 0; i < 4; i++){
        __nv_bfloat16 hb, lb; split2(xs[i], hb, lb);
        h[i] = (uint32_t)__bfloat16_as_ushort(hb);
        l[i] = (uint32_t)__bfloat16_as_ushort(lb);
    }
    *(uint2*)bhi = make_uint2(h[0] | (h[1]<<16), h[2] | (h[3]<<16));
    *(uint2*)blo = make_uint2(l[0] | (l[1]<<16), l[2] | (l[3]<<16));
}

// ---------------- embedding (+ split) ----------------
__global__ void embed_kernel(const int* __restrict__ ids, const float* __restrict__ we,
                             const float* __restrict__ pe, float* __restrict__ out,
                             __nv_bfloat16* __restrict__ outs)
{
    int e = blockIdx.x * blockDim.x + threadIdx.x;
    int n  = e >> 8;
    int hq = (e & 255) << 2;
    int s  = n & (SS - 1);
    int id = ids[n];
    float4 w = *(const float4*)(we + (size_t)id * HH + hq);
    float4 p = *(const float4*)(pe + (size_t)s  * HH + hq);
    float4 v = make_float4(w.x+p.x, w.y+p.y, w.z+p.z, w.w+p.w);
    *(float4*)(out + (size_t)n * HH + hq) = v;
    split4_store(v, outs + (size_t)n*2*HH + hq, outs + (size_t)n*2*HH + HH + hq);
}

// ---------------- weight splitter (vectorized x4) ----------------
__global__ void split_w4(const float* __restrict__ W, __nv_bfloat16* __restrict__ out,
                         int ksh, long ldo, long coff, float sgn, int total4)
{
    int i = blockIdx.x * blockDim.x + threadIdx.x;
    if (i >= total4) return;
    long e = (long)i * 4;
    long K = 1L << ksh;
    long r = e >> ksh;
    long c = e & (K - 1);
    float4 x = *(const float4*)(W + e);
    x.x *= sgn; x.y *= sgn; x.z *= sgn; x.w *= sgn;
    split4_store(x, out + r*ldo + coff + c, out + r*ldo + coff + K + c);
}

// ---------------- mma.sync GEMM: C[8192 rows x M cols] = A'[.,K'] @ B'[M,K']^T ----------------
struct GArgs {
    const __nv_bfloat16* A; const __nv_bfloat16* B;
    long lda, ldb;
    int k1sh, nst, mode;        // mode 0=BU(gamma) 1=Y 2=F1(gelu+split) 3=F2(bias)
    int amap[6], bmap[6];
    const float* vec;
    float* out0; float* out1;
    __nv_bfloat16* osplit;
};

__global__ __launch_bounds__(256, 2) void mma_gemm(const __grid_constant__ GArgs g)
{
    extern __shared__ char sm[];
    __shared__ float tab[128];
    const uint32_t sbase = smem_u32(sm);
    const int tid = threadIdx.x, lane = tid & 31, wid = tid >> 5;
    const int n0 = blockIdx.y * 128;     // token rows
    const int m0 = blockIdx.x * 128;     // output cols

    if (tid < 128){
        if (g.mode == 0)
            tab[tid] = sqrtf(fmaxf(1.f - expf(-2.f * expf(g.vec[(m0 + tid) & (HH-1)])), 0.f));
        else if (g.mode >= 2)
            tab[tid] = g.vec[m0 + tid];
    }

    // cp.async mapping: thread -> row tid>>1, chunk pair (tid&1)*2 (32B per thread per tile)
    const int arow = tid >> 1;
    const int ac0  = (tid & 1) * 2;
    const __nv_bfloat16* gA = g.A + (size_t)(n0 + arow) * g.lda + ac0*8;
    const __nv_bfloat16* gB = g.B + (size_t)(m0 + arow) * g.ldb + ac0*8;
    const uint32_t dA = (uint32_t)(arow*PITCH + ac0*16);
    const uint32_t dB = (uint32_t)(A_BYTES + arow*PITCH + ac0*16);

    const int k1m = (1 << g.k1sh) - 1;
    auto load_stage = [&](int s, uint32_t base){
        int k0 = s << 5;                          // BK=32 elements
        int seg = k0 >> g.k1sh;
        long ka = ((long)g.amap[seg] << g.k1sh) + (k0 & k1m);
        long kb = ((long)g.bmap[seg] << g.k1sh) + (k0 & k1m);
        cpa16(base + dA,      gA + ka);
        cpa16(base + dA + 16, gA + ka + 8);
        cpa16(base + dB,      gB + kb);
        cpa16(base + dB + 16, gB + kb + 8);
        CPA_COMMIT();
    };

    // warp layout: 2 (M) x 4 (N); warp tile 64x32
    const int warp_m = wid & 1, warp_n = wid >> 1;
    const int ra = (lane & 7) + (((lane >> 3) & 1) << 3);
    const int ca = (lane >> 4) * 16;
    const int rb = (lane & 7) + (((lane >> 4) & 1) << 3);
    const int cb = ((lane >> 3) & 1) * 16;
    uint32_t aoff[4], boff[2];
    #pragma unroll
    for (int mt = 0; mt < 4; mt++)
        aoff[mt] = (uint32_t)((warp_m*64 + mt*16 + ra) * PITCH + ca);
    #pragma unroll
    for (int ntp = 0; ntp < 2; ntp++)
        boff[ntp] = (uint32_t)(A_BYTES + (warp_n*32 + ntp*16 + rb) * PITCH + cb);

    float acc[4][4][4];
    #pragma unroll
    for (int i = 0; i < 4; i++)
        #pragma unroll
        for (int j = 0; j < 4; j++)
            #pragma unroll
            for (int r = 0; r < 4; r++) acc[i][j][r] = 0.f;

    load_stage(0, sbase);
    load_stage(1, sbase + STG_BYTES);
    load_stage(2, sbase + 2*STG_BYTES);
    load_stage(3, sbase + 3*STG_BYTES);

    const int nst = g.nst;
    int buf = 0, lbuf = 4;
    for (int i = 0; i < nst; i++){
        CPA_WAIT3();
        __syncthreads();
        uint32_t sb0 = sbase + (uint32_t)buf * STG_BYTES;
        #pragma unroll
        for (int s = 0; s < 2; s++){             // two k16 steps per stage
            uint32_t a[4][4], b[4][2];
            #pragma unroll
            for (int mt = 0; mt < 4; mt++)
                ldsm4(a[mt][0], a[mt][1], a[mt][2], a[mt][3], sb0 + aoff[mt] + s*32);
            #pragma unroll
            for (int ntp = 0; ntp < 2; ntp++){
                uint32_t r0, r1, r2, r3;
                ldsm4(r0, r1, r2, r3, sb0 + boff[ntp] + s*32);
                b[2*ntp][0] = r0;   b[2*ntp][1] = r1;
                b[2*ntp+1][0] = r2; b[2*ntp+1][1] = r3;
            }
            #pragma unroll
            for (int mt = 0; mt < 4; mt++)
                #pragma unroll
                for (int nt = 0; nt < 4; nt++)
                    mma16816(acc[mt][nt], a[mt], b[nt]);
        }
        int j = i + NSTAGE - 1;
        if (j < nst) load_stage(j, sbase + (uint32_t)lbuf * STG_BYTES);
        else CPA_COMMIT();
        if (++buf == NSTAGE) buf = 0;
        if (++lbuf == NSTAGE) lbuf = 0;
    }

    // epilogue
    const int rbase = n0 + warp_m*64 + (lane >> 2);
    const int cbase = warp_n*32 + (lane & 3)*2;
    #pragma unroll
    for (int mt = 0; mt < 4; mt++){
        #pragma unroll
        for (int nt = 0; nt < 4; nt++){
            int cl = cbase + nt*8;
            int col = m0 + cl;
            #pragma unroll
            for (int h = 0; h < 2; h++){
                int row = rbase + mt*16 + h*8;
                float v0 = acc[mt][nt][h*2+0];
                float v1 = acc[mt][nt][h*2+1];
                if (g.mode == 0){
                    float* dst = (col < HH) ? g.out0 : g.out1;
                    int cm = col & (HH-1);
                    *(float2*)(dst + (size_t)row*HH + cm) =
                        make_float2(v0 * tab[cl], v1 * tab[cl+1]);
                } else if (g.mode == 1){
                    *(float2*)(g.out0 + (size_t)row*HH + col) = make_float2(v0, v1);
                } else if (g.mode == 2){
                    float x0 = v0 + tab[cl], x1 = v1 + tab[cl+1];
                    x0 = x0 * normcdff(x0);                 // exact GELU
                    x1 = x1 * normcdff(x1);
                    __nv_bfloat16 h0, l0, h1, l1;
                    split2(x0, h0, l0); split2(x1, h1, l1);
                    uint32_t hw = (uint32_t)__bfloat16_as_ushort(h0) | ((uint32_t)__bfloat16_as_ushort(h1) << 16);
                    uint32_t lw = (uint32_t)__bfloat16_as_ushort(l0) | ((uint32_t)__bfloat16_as_ushort(l1) << 16);
                    size_t bh = (size_t)row * (2*FF) + col;
                    *(uint32_t*)(g.osplit + bh)      = hw;
                    *(uint32_t*)(g.osplit + bh + FF) = lw;
                } else {
                    *(float2*)(g.out0 + (size_t)row*HH + col) =
                        make_float2(v0 + tab[cl], v1 + tab[cl+1]);
                }
            }
        }
    }
}

// ---------------- chunked complex scan ----------------
__device__ __forceinline__ void lam_of(const float* nul, const float* thl, int u,
                                       float& lre, float& lim)
{
    float r   = expf(-expf(nul[u]));
    float ang = expf(thl[u]);
    lre = r * cosf(ang);
    lim = r * sinf(ang);
}

// pass1: per-chunk inclusive local carry only (no writeback)
__global__ void scan_pass1(const float* __restrict__ nul, const float* __restrict__ thl,
                           const float* __restrict__ tre, const float* __restrict__ tim,
                           float2* __restrict__ carry)
{
    int t = blockIdx.x * blockDim.x + threadIdx.x;
    int u = t & (HH - 1);
    int rest = t >> 10;
    int c = rest & (NCHUNK - 1);
    int b = rest >> 5;
    float lre, lim; lam_of(nul, thl, u, lre, lim);
    size_t base = ((size_t)b * SS + (size_t)c * CLEN) * HH + u;
    float sre = 0.f, sim = 0.f;
    #pragma unroll 4
    for (int i = 0; i < CLEN; i++) {
        size_t ix = base + (size_t)i * HH;
        float xr = tre[ix], xi = tim[ix];
        float nr = fmaf(lre, sre, fmaf(-lim, sim, xr));
        float ni = fmaf(lre, sim, fmaf( lim, sre, xi));
        sre = nr; sim = ni;
    }
    carry[(b * NCHUNK + c) * HH + u] = make_float2(sre, sim);
}

// pass3 (pass2 folded in): compute exclusive chunk carry from chunk carries,
// redo local scan, emit bf16 splits
__global__ void scan_pass3(const float* __restrict__ nul, const float* __restrict__ thl,
                           const float* __restrict__ tre, const float* __restrict__ tim,
                           const float2* __restrict__ carry, __nv_bfloat16* __restrict__ sp)
{
    int t = blockIdx.x * blockDim.x + threadIdx.x;
    int u = t & (HH - 1);
    int rest = t >> 10;
    int c = rest & (NCHUNK - 1);
    int b = rest >> 5;
    float lre, lim; lam_of(nul, thl, u, lre, lim);
    // lamC = lam^CLEN
    float pr = 1.f, pi = 0.f;
    #pragma unroll
    for (int i = 0; i < CLEN; i++) {
        float nr = pr * lre - pi * lim;
        float ni = pr * lim + pi * lre;
        pr = nr; pi = ni;
    }
    // exclusive carry: cc = sum_{j<c} lamC^(c-1-j) * carry_j   (Horner, j ascending)
    float ccr = 0.f, cci = 0.f;
    for (int j = 0; j < c; j++) {
        float2 f = carry[(b * NCHUNK + j) * HH + u];
        float nr = fmaf(pr, ccr, fmaf(-pi, cci, f.x));
        float ni = fmaf(pr, cci, fmaf( pi, ccr, f.y));
        ccr = nr; cci = ni;
    }
    size_t base = ((size_t)b * SS + (size_t)c * CLEN) * HH + u;
    size_t nbase = (size_t)b * SS + (size_t)c * CLEN;
    float sre = ccr, sim = cci;
    for (int i = 0; i < CLEN; i++) {
        size_t ix = base + (size_t)i * HH;
        float xr = tre[ix], xi = tim[ix];
        float nr = fmaf(lre, sre, fmaf(-lim, sim, xr));
        float ni = fmaf(lre, sim, fmaf( lim, sre, xi));
        sre = nr; sim = ni;
        size_t ro = (nbase + i) * (4*HH) + u;
        __nv_bfloat16 h1, l1, h2, l2;
        split2(sre, h1, l1); split2(sim, h2, l2);
        sp[ro]        = h1;
        sp[ro + HH]   = l1;
        sp[ro + 2*HH] = h2;
        sp[ro + 3*HH] = l2;
    }
}

// ---------------- fused residual + RMS-LN (+ split output) ----------------
__global__ void ln_kernel(const float* __restrict__ h, const float* __restrict__ y,
                          const float* __restrict__ Dl, const float* __restrict__ bias,
                          float* __restrict__ out, __nv_bfloat16* __restrict__ osplit)
{
    int n = blockIdx.x;
    int t = threadIdx.x;
    size_t idx = (size_t)n * HH + (t << 2);
    float4 hv = *(const float4*)(h + idx);
    float4 yv = *(const float4*)(y + idx);
    float4 z;
    if (Dl) {
        float4 dv = *(const float4*)(Dl + (t << 2));
        z.x = fmaf(hv.x, 1.f + dv.x, yv.x);
        z.y = fmaf(hv.y, 1.f + dv.y, yv.y);
        z.z = fmaf(hv.z, 1.f + dv.z, yv.z);
        z.w = fmaf(hv.w, 1.f + dv.w, yv.w);
    } else {
        z.x = hv.x + yv.x; z.y = hv.y + yv.y; z.z = hv.z + yv.z; z.w = hv.w + yv.w;
    }
    float s = z.x*z.x + z.y*z.y + z.z*z.z + z.w*z.w;
    #pragma unroll
    for (int o = 16; o; o >>= 1) s += __shfl_xor_sync(0xffffffffu, s, o);
    __shared__ float red[8];
    if ((t & 31) == 0) red[t >> 5] = s;
    __syncthreads();
    float tot = red[0]+red[1]+red[2]+red[3]+red[4]+red[5]+red[6]+red[7];
    float inv = rsqrtf(tot * (1.f / (float)HH) + 1e-12f);
    float4 bv = *(const float4*)(bias + (t << 2));
    float4 o4 = make_float4(fmaf(z.x, inv, bv.x), fmaf(z.y, inv, bv.y),
                            fmaf(z.z, inv, bv.z), fmaf(z.w, inv, bv.w));
    *(float4*)(out + idx) = o4;
    split4_store(o4, osplit + (size_t)n*2*HH + (t<<2),
                     osplit + (size_t)n*2*HH + HH + (t<<2));
}

// ---------------- launch ----------------
extern "C" void kernel_launch(void* const* d_in, const int* in_sizes, int n_in,
                              void* d_out, int out_size)
{
    const int*   ids = (const int*)  d_in[0];
    const float* we  = (const float*)d_in[1];
    const float* pe  = (const float*)d_in[2];
    const float* nu  = (const float*)d_in[3];
    const float* th  = (const float*)d_in[4];
    const float* Bre = (const float*)d_in[5];
    const float* Bim = (const float*)d_in[6];
    const float* Cre = (const float*)d_in[7];
    const float* Cim = (const float*)d_in[8];
    const float* Dp  = (const float*)d_in[9];
    const float* rnb = (const float*)d_in[10];
    const float* w1  = (const float*)d_in[11];
    const float* b1  = (const float*)d_in[12];
    const float* w2  = (const float*)d_in[13];
    const float* b2  = (const float*)d_in[14];
    const float* fnb = (const float*)d_in[15];
    float* out = (float*)d_out;

    float *ph, *ptre, *ptim, *py; float2* pc;
    __nv_bfloat16 *phs, *psp, *pfs, *pwbu, *pwy, *pwf1, *pwf2;
    cudaGetSymbolAddress((void**)&ph,   g_h);
    cudaGetSymbolAddress((void**)&ptre, g_tre);
    cudaGetSymbolAddress((void**)&ptim, g_tim);
    cudaGetSymbolAddress((void**)&py,   g_y);
    cudaGetSymbolAddress((void**)&pc,   g_carry);
    cudaGetSymbolAddress((void**)&phs,  g_hs);
    cudaGetSymbolAddress((void**)&psp,  g_sp);
    cudaGetSymbolAddress((void**)&pfs,  g_fs);
    cudaGetSymbolAddress((void**)&pwbu, g_wbu);
    cudaGetSymbolAddress((void**)&pwy,  g_wy);
    cudaGetSymbolAddress((void**)&pwf1, g_wf1);
    cudaGetSymbolAddress((void**)&pwf2, g_wf2);

    cudaFuncSetAttribute(mma_gemm, cudaFuncAttributeMaxDynamicSharedMemorySize, SMEM_SZ);

    // weight splits (hi|lo) bf16, vectorized x4
    for (int l = 0; l < LL; l++) {
        size_t hh = (size_t)HH*HH;
        split_w4<<<HH*HH/4/256, 256>>>(Bre + l*hh, pwbu + (size_t)l*2048*2048,              10, 2048, 0,    1.f, HH*HH/4);
        split_w4<<<HH*HH/4/256, 256>>>(Bim + l*hh, pwbu + (size_t)l*2048*2048 + 1024L*2048, 10, 2048, 0,    1.f, HH*HH/4);
        split_w4<<<HH*HH/4/256, 256>>>(Cre + l*hh, pwy  + (size_t)l*1024*4096,              10, 4096, 0,    1.f, HH*HH/4);
        split_w4<<<HH*HH/4/256, 256>>>(Cim + l*hh, pwy  + (size_t)l*1024*4096,              10, 4096, 2048,-1.f, HH*HH/4);
        split_w4<<<FF*HH/4/256, 256>>>(w1 + (size_t)l*FF*HH, pwf1 + (size_t)l*4096*2048,    10, 2048, 0,    1.f, FF*HH/4);
        split_w4<<<FF*HH/4/256, 256>>>(w2 + (size_t)l*HH*FF, pwf2 + (size_t)l*1024*8192,    12, 8192, 0,    1.f, HH*FF/4);
    }

    embed_kernel<<<(size_t)NN*HH/4/256, 256>>>(ids, we, pe, ph, phs);

    int am1[6] = {0,0,1,0,0,0}, bm1[6] = {0,1,0,0,0,0};          // 3-seg: hihi, hilo, lohi
    int am2[6] = {0,0,1,2,2,3}, bm2[6] = {0,1,0,2,3,2};          // 6-seg complex

    for (int l = 0; l < LL; l++) {
        const float* nul = nu + l*HH;
        const float* thl = th + l*HH;

        // BU: [h_hi|h_lo] x [Bre;Bim] -> tre/tim (gamma fused). M=2048, K'=3072
        GArgs a = {};
        a.A = phs; a.B = pwbu + (size_t)l*2048*2048;
        a.lda = 2048; a.ldb = 2048;
        a.k1sh = 10; a.nst = 96; a.mode = 0;
        for (int i = 0; i < 6; i++){ a.amap[i] = am1[i]; a.bmap[i] = bm1[i]; }
        a.vec = nul; a.out0 = ptre; a.out1 = ptim;
        mma_gemm<<<dim3(16, 64), 256, SMEM_SZ>>>(a);

        scan_pass1<<<BB*NCHUNK*HH/256, 256>>>(nul, thl, ptre, ptim, pc);
        scan_pass3<<<BB*NCHUNK*HH/256, 256>>>(nul, thl, ptre, ptim, pc, psp);

        // Y: [re_hi|re_lo|im_hi|im_lo] x [Cre|-Cim] -> y. M=1024, K'=6144
        a = GArgs{};
        a.A = psp; a.B = pwy + (size_t)l*1024*4096;
        a.lda = 4096; a.ldb = 4096;
        a.k1sh = 10; a.nst = 192; a.mode = 1;
        for (int i = 0; i < 6; i++){ a.amap[i] = am2[i]; a.bmap[i] = bm2[i]; }
        a.out0 = py;
        mma_gemm<<<dim3(8, 64), 256, SMEM_SZ>>>(a);

        ln_kernel<<<NN, 256>>>(ph, py, Dp + l*HH, rnb + l*HH, ph, phs);

        // FFN1: h_split x w1_split -> gelu -> g_fs. M=4096, K'=3072
        a = GArgs{};
        a.A = phs; a.B = pwf1 + (size_t)l*4096*2048;
        a.lda = 2048; a.ldb = 2048;
        a.k1sh = 10; a.nst = 96; a.mode = 2;
        for (int i = 0; i < 6; i++){ a.amap[i] = am1[i]; a.bmap[i] = bm1[i]; }
        a.vec = b1 + l*FF; a.osplit = pfs;
        mma_gemm<<<dim3(32, 64), 256, SMEM_SZ>>>(a);

        // FFN2: g_fs x w2_split + bias -> y. M=1024, K'=12288
        a = GArgs{};
        a.A = pfs; a.B = pwf2 + (size_t)l*1024*8192;
        a.lda = 8192; a.ldb = 8192;
        a.k1sh = 12; a.nst = 384; a.mode = 3;
        for (int i = 0; i < 6; i++){ a.amap[i] = am1[i]; a.bmap[i] = bm1[i]; }
        a.vec = b2 + l*HH; a.out0 = py;
        mma_gemm<<<dim3(8, 64), 256, SMEM_SZ>>>(a);

        float* lnout = (l == LL-1) ? out : ph;
        ln_kernel<<<NN, 256>>>(ph, py, nullptr, fnb + l*HH, lnout, phs);
    }
}

// round 13
// speedup vs baseline: 1.0891x; 1.0098x over previous
#include <cuda_runtime.h>
#include <cuda_bf16.h>
#include <cstdint>

#define BB 4
#define SS 2048
#define HH 1024
#define LL 4
#define FF 4096
#define NN (BB*SS)
#define NCHUNK 32
#define CLEN (SS/NCHUNK)

// GEMM tiling (R10 shape): BM=128, BN=128, BK=32, 256 thr (2x4 warps, 64x32 warp tile), 4 stages
#define PITCH 80                      // 64B data + 16B pad per 32-bf16 row
#define A_BYTES (128*PITCH)           // 10240
#define STG_BYTES (2*A_BYTES)         // 20480 (A + B)
#define NSTAGE 4
#define SMEM_SZ (NSTAGE*STG_BYTES)    // 81920

// ---------------- scratch ----------------
__device__ __align__(256) float g_h  [(size_t)NN*HH];
__device__ __align__(256) float g_tre[(size_t)NN*HH];
__device__ __align__(256) float g_tim[(size_t)NN*HH];
__device__ __align__(256) float g_y  [(size_t)NN*HH];
__device__ float2 g_carry[BB*NCHUNK*HH];
__device__ __align__(256) __nv_bfloat16 g_hs[(size_t)NN*2*HH];   // h split [hi|lo]
__device__ __align__(256) __nv_bfloat16 g_sp[(size_t)NN*4*HH];   // scan out [re_hi|re_lo|im_hi|im_lo]
__device__ __align__(256) __nv_bfloat16 g_fs[(size_t)NN*2*FF];   // gelu out [hi|lo]
__device__ __align__(256) __nv_bfloat16 g_wbu[(size_t)LL*2048*2048];
__device__ __align__(256) __nv_bfloat16 g_wy [(size_t)LL*1024*4096];
__device__ __align__(256) __nv_bfloat16 g_wf1[(size_t)LL*4096*2048];
__device__ __align__(256) __nv_bfloat16 g_wf2[(size_t)LL*1024*8192];

// ---------------- helpers ----------------
__device__ __forceinline__ uint32_t smem_u32(const void* p){
    uint32_t a;
    asm("{ .reg .u64 t; cvta.to.shared.u64 t, %1; cvt.u32.u64 %0, t; }" : "=r"(a) : "l"(p));
    return a;
}
#define CPA_COMMIT() asm volatile("cp.async.commit_group;" ::: "memory")
#define CPA_WAIT2()  asm volatile("cp.async.wait_group 2;" ::: "memory")
__device__ __forceinline__ void cpa16(uint32_t d, const void* s){
    asm volatile("cp.async.cg.shared.global [%0], [%1], 16;" :: "r"(d), "l"(s));
}
__device__ __forceinline__ void ldsm4(uint32_t& r0, uint32_t& r1, uint32_t& r2, uint32_t& r3, uint32_t a){
    asm volatile("ldmatrix.sync.aligned.m8n8.x4.shared.b16 {%0,%1,%2,%3}, [%4];"
        : "=r"(r0), "=r"(r1), "=r"(r2), "=r"(r3) : "r"(a));
}
__device__ __forceinline__ void mma16816(float* d, const uint32_t* a, const uint32_t* b){
    asm volatile("mma.sync.aligned.m16n8k16.row.col.f32.bf16.bf16.f32 "
        "{%0,%1,%2,%3}, {%4,%5,%6,%7}, {%8,%9}, {%0,%1,%2,%3};"
        : "+f"(d[0]), "+f"(d[1]), "+f"(d[2]), "+f"(d[3])
        : "r"(a[0]), "r"(a[1]), "r"(a[2]), "r"(a[3]), "r"(b[0]), "r"(b[1]));
}
__device__ __forceinline__ void split2(float x, __nv_bfloat16& hi, __nv_bfloat16& lo){
    hi = __float2bfloat16(x);
    lo = __float2bfloat16(x - __bfloat162float(hi));
}
__device__ __forceinline__ void split4_store(float4 v, __nv_bfloat16* bhi, __nv_bfloat16* blo){
    float xs[4] = {v.x, v.y, v.z, v.w};
    uint32_t h[4], l[4];
    #pragma unroll
    for (int i = 0; i < 4; i++){
        __nv_bfloat16 hb, lb; split2(xs[i], hb, lb);
        h[i] = (uint32_t)__bfloat16_as_ushort(hb);
        l[i] = (uint32_t)__bfloat16_as_ushort(lb);
    }
    *(uint2*)bhi = make_uint2(h[0] | (h[1]<<16), h[2] | (h[3]<<16));
    *(uint2*)blo = make_uint2(l[0] | (l[1]<<16), l[2] | (l[3]<<16));
}

// ---------------- embedding (+ split) ----------------
__global__ void embed_kernel(const int* __restrict__ ids, const float* __restrict__ we,
                             const float* __restrict__ pe, float* __restrict__ out,
                             __nv_bfloat16* __restrict__ outs)
{
    int e = blockIdx.x * blockDim.x + threadIdx.x;
    int n  = e >> 8;
    int hq = (e & 255) << 2;
    int s  = n & (SS - 1);
    int id = ids[n];
    float4 w = *(const float4*)(we + (size_t)id * HH + hq);
    float4 p = *(const float4*)(pe + (size_t)s  * HH + hq);
    float4 v = make_float4(w.x+p.x, w.y+p.y, w.z+p.z, w.w+p.w);
    *(float4*)(out + (size_t)n * HH + hq) = v;
    split4_store(v, outs + (size_t)n*2*HH + hq, outs + (size_t)n*2*HH + HH + hq);
}

// ---------------- batched weight splitter: ALL 24 jobs in one launch ----------------
// per layer, blockIdx.x decodes: [0,1024) Bre  [1024,2048) Bim  [2048,3072) Cre
//                                [3072,4096) Cim  [4096,8192) w1  [8192,12288) w2
__global__ void split_all(const float* __restrict__ Bre, const float* __restrict__ Bim,
                          const float* __restrict__ Cre, const float* __restrict__ Cim,
                          const float* __restrict__ w1,  const float* __restrict__ w2,
                          __nv_bfloat16* __restrict__ wbu, __nv_bfloat16* __restrict__ wy,
                          __nv_bfloat16* __restrict__ wf1, __nv_bfloat16* __restrict__ wf2)
{
    const int blk = blockIdx.x;
    const int l   = blockIdx.y;
    const size_t hh = (size_t)HH*HH;
    const float* src; __nv_bfloat16* dst;
    int ksh; long ldo, coff; float sgn; int idx0;
    if (blk < 1024){        src = Bre + l*hh; dst = wbu + (size_t)l*2048*2048;
                            ksh = 10; ldo = 2048; coff = 0;    sgn = 1.f; idx0 = blk; }
    else if (blk < 2048){   src = Bim + l*hh; dst = wbu + (size_t)l*2048*2048 + 1024L*2048;
                            ksh = 10; ldo = 2048; coff = 0;    sgn = 1.f; idx0 = blk - 1024; }
    else if (blk < 3072){   src = Cre + l*hh; dst = wy  + (size_t)l*1024*4096;
                            ksh = 10; ldo = 4096; coff = 0;    sgn = 1.f; idx0 = blk - 2048; }
    else if (blk < 4096){   src = Cim + l*hh; dst = wy  + (size_t)l*1024*4096;
                            ksh = 10; ldo = 4096; coff = 2048; sgn = -1.f; idx0 = blk - 3072; }
    else if (blk < 8192){   src = w1 + (size_t)l*FF*HH; dst = wf1 + (size_t)l*4096*2048;
                            ksh = 10; ldo = 2048; coff = 0;    sgn = 1.f; idx0 = blk - 4096; }
    else{                   src = w2 + (size_t)l*HH*FF; dst = wf2 + (size_t)l*1024*8192;
                            ksh = 12; ldo = 8192; coff = 0;    sgn = 1.f; idx0 = blk - 8192; }
    long e = ((long)idx0 * 256 + threadIdx.x) * 4;
    long K = 1L << ksh;
    long r = e >> ksh;
    long c = e & (K - 1);
    float4 x = *(const float4*)(src + e);
    x.x *= sgn; x.y *= sgn; x.z *= sgn; x.w *= sgn;
    split4_store(x, dst + r*ldo + coff + c, dst + r*ldo + coff + K + c);
}

// ---------------- mma.sync GEMM: C[8192 rows x M cols] = A'[.,K'] @ B'[M,K']^T ----------------
struct GArgs {
    const __nv_bfloat16* A; const __nv_bfloat16* B;
    long lda, ldb;
    int k1sh, nst, mode;        // mode 0=BU(gamma) 1=Y 2=F1(gelu+split) 3=F2(bias)
    int amap[6], bmap[6];
    const float* vec;
    float* out0; float* out1;
    __nv_bfloat16* osplit;
};

__global__ __launch_bounds__(256, 2) void mma_gemm(const __grid_constant__ GArgs g)
{
    extern __shared__ char sm[];
    __shared__ float tab[128];
    const uint32_t sbase = smem_u32(sm);
    const int tid = threadIdx.x, lane = tid & 31, wid = tid >> 5;
    const int n0 = blockIdx.y * 128;     // token rows
    const int m0 = blockIdx.x * 128;     // output cols

    if (tid < 128){
        if (g.mode == 0)
            tab[tid] = sqrtf(fmaxf(1.f - expf(-2.f * expf(g.vec[(m0 + tid) & (HH-1)])), 0.f));
        else if (g.mode >= 2)
            tab[tid] = g.vec[m0 + tid];
    }

    // cp.async mapping: thread -> row tid>>1, chunk pair (tid&1)*2 (32B per thread per tile)
    const int arow = tid >> 1;
    const int ac0  = (tid & 1) * 2;
    const __nv_bfloat16* gA = g.A + (size_t)(n0 + arow) * g.lda + ac0*8;
    const __nv_bfloat16* gB = g.B + (size_t)(m0 + arow) * g.ldb + ac0*8;
    const uint32_t dA = (uint32_t)(arow*PITCH + ac0*16);
    const uint32_t dB = (uint32_t)(A_BYTES + arow*PITCH + ac0*16);

    const int k1m = (1 << g.k1sh) - 1;
    auto load_stage = [&](int s){
        int k0 = s << 5;                          // BK=32 elements
        int seg = k0 >> g.k1sh;
        long ka = ((long)g.amap[seg] << g.k1sh) + (k0 & k1m);
        long kb = ((long)g.bmap[seg] << g.k1sh) + (k0 & k1m);
        uint32_t base = sbase + (uint32_t)(s & (NSTAGE-1)) * STG_BYTES;
        cpa16(base + dA,      gA + ka);
        cpa16(base + dA + 16, gA + ka + 8);
        cpa16(base + dB,      gB + kb);
        cpa16(base + dB + 16, gB + kb + 8);
        CPA_COMMIT();
    };

    // warp layout: 2 (M) x 4 (N); warp tile 64x32
    const int warp_m = wid & 1, warp_n = wid >> 1;
    const int ra = (lane & 7) + (((lane >> 3) & 1) << 3);
    const int ca = (lane >> 4) * 16;
    const int rb = (lane & 7) + (((lane >> 4) & 1) << 3);
    const int cb = ((lane >> 3) & 1) * 16;
    uint32_t aoff[4], boff[2];
    #pragma unroll
    for (int mt = 0; mt < 4; mt++)
        aoff[mt] = (uint32_t)((warp_m*64 + mt*16 + ra) * PITCH + ca);
    #pragma unroll
    for (int ntp = 0; ntp < 2; ntp++)
        boff[ntp] = (uint32_t)(A_BYTES + (warp_n*32 + ntp*16 + rb) * PITCH + cb);

    float acc[4][4][4];
    #pragma unroll
    for (int i = 0; i < 4; i++)
        #pragma unroll
        for (int j = 0; j < 4; j++)
            #pragma unroll
            for (int r = 0; r < 4; r++) acc[i][j][r] = 0.f;

    for (int s = 0; s < NSTAGE-1; s++) load_stage(s);

    const int nst = g.nst;
    for (int i = 0; i < nst; i++){
        CPA_WAIT2();
        __syncthreads();
        uint32_t sb0 = sbase + (uint32_t)(i & (NSTAGE-1)) * STG_BYTES;
        #pragma unroll
        for (int s = 0; s < 2; s++){             // two k16 steps per stage
            uint32_t a[4][4], b[4][2];
            #pragma unroll
            for (int mt = 0; mt < 4; mt++)
                ldsm4(a[mt][0], a[mt][1], a[mt][2], a[mt][3], sb0 + aoff[mt] + s*32);
            #pragma unroll
            for (int ntp = 0; ntp < 2; ntp++){
                uint32_t r0, r1, r2, r3;
                ldsm4(r0, r1, r2, r3, sb0 + boff[ntp] + s*32);
                b[2*ntp][0] = r0;   b[2*ntp][1] = r1;
                b[2*ntp+1][0] = r2; b[2*ntp+1][1] = r3;
            }
            #pragma unroll
            for (int mt = 0; mt < 4; mt++)
                #pragma unroll
                for (int nt = 0; nt < 4; nt++)
                    mma16816(acc[mt][nt], a[mt], b[nt]);
        }
        int j = i + NSTAGE - 1;
        if (j < nst) load_stage(j);
        else CPA_COMMIT();
    }

    // epilogue
    const int rbase = n0 + warp_m*64 + (lane >> 2);
    const int cbase = warp_n*32 + (lane & 3)*2;
    #pragma unroll
    for (int mt = 0; mt < 4; mt++){
        #pragma unroll
        for (int nt = 0; nt < 4; nt++){
            int cl = cbase + nt*8;
            int col = m0 + cl;
            #pragma unroll
            for (int h = 0; h < 2; h++){
                int row = rbase + mt*16 + h*8;
                float v0 = acc[mt][nt][h*2+0];
                float v1 = acc[mt][nt][h*2+1];
                if (g.mode == 0){
                    float* dst = (col < HH) ? g.out0 : g.out1;
                    int cm = col & (HH-1);
                    *(float2*)(dst + (size_t)row*HH + cm) =
                        make_float2(v0 * tab[cl], v1 * tab[cl+1]);
                } else if (g.mode == 1){
                    *(float2*)(g.out0 + (size_t)row*HH + col) = make_float2(v0, v1);
                } else if (g.mode == 2){
                    float x0 = v0 + tab[cl], x1 = v1 + tab[cl+1];
                    x0 = x0 * normcdff(x0);                 // exact GELU
                    x1 = x1 * normcdff(x1);
                    __nv_bfloat16 h0, l0, h1, l1;
                    split2(x0, h0, l0); split2(x1, h1, l1);
                    uint32_t hw = (uint32_t)__bfloat16_as_ushort(h0) | ((uint32_t)__bfloat16_as_ushort(h1) << 16);
                    uint32_t lw = (uint32_t)__bfloat16_as_ushort(l0) | ((uint32_t)__bfloat16_as_ushort(l1) << 16);
                    size_t bh = (size_t)row * (2*FF) + col;
                    *(uint32_t*)(g.osplit + bh)      = hw;
                    *(uint32_t*)(g.osplit + bh + FF) = lw;
                } else {
                    *(float2*)(g.out0 + (size_t)row*HH + col) =
                        make_float2(v0 + tab[cl], v1 + tab[cl+1]);
                }
            }
        }
    }
}

// ---------------- chunked complex scan ----------------
__device__ __forceinline__ void lam_of(const float* nul, const float* thl, int u,
                                       float& lre, float& lim)
{
    float r   = expf(-expf(nul[u]));
    float ang = expf(thl[u]);
    lre = r * cosf(ang);
    lim = r * sinf(ang);
}

// pass1: per-chunk inclusive local carry only (no writeback)
__global__ void scan_pass1(const float* __restrict__ nul, const float* __restrict__ thl,
                           const float* __restrict__ tre, const float* __restrict__ tim,
                           float2* __restrict__ carry)
{
    int t = blockIdx.x * blockDim.x + threadIdx.x;
    int u = t & (HH - 1);
    int rest = t >> 10;
    int c = rest & (NCHUNK - 1);
    int b = rest >> 5;
    float lre, lim; lam_of(nul, thl, u, lre, lim);
    size_t base = ((size_t)b * SS + (size_t)c * CLEN) * HH + u;
    float sre = 0.f, sim = 0.f;
    #pragma unroll 4
    for (int i = 0; i < CLEN; i++) {
        size_t ix = base + (size_t)i * HH;
        float xr = tre[ix], xi = tim[ix];
        float nr = fmaf(lre, sre, fmaf(-lim, sim, xr));
        float ni = fmaf(lre, sim, fmaf( lim, sre, xi));
        sre = nr; sim = ni;
    }
    carry[(b * NCHUNK + c) * HH + u] = make_float2(sre, sim);
}

// pass3 (pass2 folded in): exclusive chunk carry via Horner over chunk carries,
// redo local scan, emit bf16 splits
__global__ void scan_pass3(const float* __restrict__ nul, const float* __restrict__ thl,
                           const float* __restrict__ tre, const float* __restrict__ tim,
                           const float2* __restrict__ carry, __nv_bfloat16* __restrict__ sp)
{
    int t = blockIdx.x * blockDim.x + threadIdx.x;
    int u = t & (HH - 1);
    int rest = t >> 10;
    int c = rest & (NCHUNK - 1);
    int b = rest >> 5;
    float lre, lim; lam_of(nul, thl, u, lre, lim);
    // lamC = lam^CLEN
    float pr = 1.f, pi = 0.f;
    #pragma unroll
    for (int i = 0; i < CLEN; i++) {
        float nr = pr * lre - pi * lim;
        float ni = pr * lim + pi * lre;
        pr = nr; pi = ni;
    }
    // exclusive carry (Horner, j ascending)
    float ccr = 0.f, cci = 0.f;
    for (int j = 0; j < c; j++) {
        float2 f = carry[(b * NCHUNK + j) * HH + u];
        float nr = fmaf(pr, ccr, fmaf(-pi, cci, f.x));
        float ni = fmaf(pr, cci, fmaf( pi, ccr, f.y));
        ccr = nr; cci = ni;
    }
    size_t base = ((size_t)b * SS + (size_t)c * CLEN) * HH + u;
    size_t nbase = (size_t)b * SS + (size_t)c * CLEN;
    float sre = ccr, sim = cci;
    for (int i = 0; i < CLEN; i++) {
        size_t ix = base + (size_t)i * HH;
        float xr = tre[ix], xi = tim[ix];
        float nr = fmaf(lre, sre, fmaf(-lim, sim, xr));
        float ni = fmaf(lre, sim, fmaf( lim, sre, xi));
        sre = nr; sim = ni;
        size_t ro = (nbase + i) * (4*HH) + u;
        __nv_bfloat16 h1, l1, h2, l2;
        split2(sre, h1, l1); split2(sim, h2, l2);
        sp[ro]        = h1;
        sp[ro + HH]   = l1;
        sp[ro + 2*HH] = h2;
        sp[ro + 3*HH] = l2;
    }
}

// ---------------- fused residual + RMS-LN (+ split output) ----------------
__global__ void ln_kernel(const float* __restrict__ h, const float* __restrict__ y,
                          const float* __restrict__ Dl, const float* __restrict__ bias,
                          float* __restrict__ out, __nv_bfloat16* __restrict__ osplit)
{
    int n = blockIdx.x;
    int t = threadIdx.x;
    size_t idx = (size_t)n * HH + (t << 2);
    float4 hv = *(const float4*)(h + idx);
    float4 yv = *(const float4*)(y + idx);
    float4 z;
    if (Dl) {
        float4 dv = *(const float4*)(Dl + (t << 2));
        z.x = fmaf(hv.x, 1.f + dv.x, yv.x);
        z.y = fmaf(hv.y, 1.f + dv.y, yv.y);
        z.z = fmaf(hv.z, 1.f + dv.z, yv.z);
        z.w = fmaf(hv.w, 1.f + dv.w, yv.w);
    } else {
        z.x = hv.x + yv.x; z.y = hv.y + yv.y; z.z = hv.z + yv.z; z.w = hv.w + yv.w;
    }
    float s = z.x*z.x + z.y*z.y + z.z*z.z + z.w*z.w;
    #pragma unroll
    for (int o = 16; o; o >>= 1) s += __shfl_xor_sync(0xffffffffu, s, o);
    __shared__ float red[8];
    if ((t & 31) == 0) red[t >> 5] = s;
    __syncthreads();
    float tot = red[0]+red[1]+red[2]+red[3]+red[4]+red[5]+red[6]+red[7];
    float inv = rsqrtf(tot * (1.f / (float)HH) + 1e-12f);
    float4 bv = *(const float4*)(bias + (t << 2));
    float4 o4 = make_float4(fmaf(z.x, inv, bv.x), fmaf(z.y, inv, bv.y),
                            fmaf(z.z, inv, bv.z), fmaf(z.w, inv, bv.w));
    *(float4*)(out + idx) = o4;
    split4_store(o4, osplit + (size_t)n*2*HH + (t<<2),
                     osplit + (size_t)n*2*HH + HH + (t<<2));
}

// ---------------- launch ----------------
extern "C" void kernel_launch(void* const* d_in, const int* in_sizes, int n_in,
                              void* d_out, int out_size)
{
    const int*   ids = (const int*)  d_in[0];
    const float* we  = (const float*)d_in[1];
    const float* pe  = (const float*)d_in[2];
    const float* nu  = (const float*)d_in[3];
    const float* th  = (const float*)d_in[4];
    const float* Bre = (const float*)d_in[5];
    const float* Bim = (const float*)d_in[6];
    const float* Cre = (const float*)d_in[7];
    const float* Cim = (const float*)d_in[8];
    const float* Dp  = (const float*)d_in[9];
    const float* rnb = (const float*)d_in[10];
    const float* w1  = (const float*)d_in[11];
    const float* b1  = (const float*)d_in[12];
    const float* w2  = (const float*)d_in[13];
    const float* b2  = (const float*)d_in[14];
    const float* fnb = (const float*)d_in[15];
    float* out = (float*)d_out;

    float *ph, *ptre, *ptim, *py; float2* pc;
    __nv_bfloat16 *phs, *psp, *pfs, *pwbu, *pwy, *pwf1, *pwf2;
    cudaGetSymbolAddress((void**)&ph,   g_h);
    cudaGetSymbolAddress((void**)&ptre, g_tre);
    cudaGetSymbolAddress((void**)&ptim, g_tim);
    cudaGetSymbolAddress((void**)&py,   g_y);
    cudaGetSymbolAddress((void**)&pc,   g_carry);
    cudaGetSymbolAddress((void**)&phs,  g_hs);
    cudaGetSymbolAddress((void**)&psp,  g_sp);
    cudaGetSymbolAddress((void**)&pfs,  g_fs);
    cudaGetSymbolAddress((void**)&pwbu, g_wbu);
    cudaGetSymbolAddress((void**)&pwy,  g_wy);
    cudaGetSymbolAddress((void**)&pwf1, g_wf1);
    cudaGetSymbolAddress((void**)&pwf2, g_wf2);

    cudaFuncSetAttribute(mma_gemm, cudaFuncAttributeMaxDynamicSharedMemorySize, SMEM_SZ);

    // all 24 weight-split jobs in ONE launch
    split_all<<<dim3(12288, LL), 256>>>(Bre, Bim, Cre, Cim, w1, w2, pwbu, pwy, pwf1, pwf2);

    embed_kernel<<<(size_t)NN*HH/4/256, 256>>>(ids, we, pe, ph, phs);

    int am1[6] = {0,0,1,0,0,0}, bm1[6] = {0,1,0,0,0,0};          // 3-seg: hihi, hilo, lohi
    int am2[6] = {0,0,1,2,2,3}, bm2[6] = {0,1,0,2,3,2};          // 6-seg complex

    for (int l = 0; l < LL; l++) {
        const float* nul = nu + l*HH;
        const float* thl = th + l*HH;

        // BU: [h_hi|h_lo] x [Bre;Bim] -> tre/tim (gamma fused). M=2048, K'=3072
        GArgs a = {};
        a.A = phs; a.B = pwbu + (size_t)l*2048*2048;
        a.lda = 2048; a.ldb = 2048;
        a.k1sh = 10; a.nst = 96; a.mode = 0;
        for (int i = 0; i < 6; i++){ a.amap[i] = am1[i]; a.bmap[i] = bm1[i]; }
        a.vec = nul; a.out0 = ptre; a.out1 = ptim;
        mma_gemm<<<dim3(16, 64), 256, SMEM_SZ>>>(a);

        scan_pass1<<<BB*NCHUNK*HH/256, 256>>>(nul, thl, ptre, ptim, pc);
        scan_pass3<<<BB*NCHUNK*HH/256, 256>>>(nul, thl, ptre, ptim, pc, psp);

        // Y: [re_hi|re_lo|im_hi|im_lo] x [Cre|-Cim] -> y. M=1024, K'=6144
        a = GArgs{};
        a.A = psp; a.B = pwy + (size_t)l*1024*4096;
        a.lda = 4096; a.ldb = 4096;
        a.k1sh = 10; a.nst = 192; a.mode = 1;
        for (int i = 0; i < 6; i++){ a.amap[i] = am2[i]; a.bmap[i] = bm2[i]; }
        a.out0 = py;
        mma_gemm<<<dim3(8, 64), 256, SMEM_SZ>>>(a);

        ln_kernel<<<NN, 256>>>(ph, py, Dp + l*HH, rnb + l*HH, ph, phs);

        // FFN1: h_split x w1_split -> gelu -> g_fs. M=4096, K'=3072
        a = GArgs{};
        a.A = phs; a.B = pwf1 + (size_t)l*4096*2048;
        a.lda = 2048; a.ldb = 2048;
        a.k1sh = 10; a.nst = 96; a.mode = 2;
        for (int i = 0; i < 6; i++){ a.amap[i] = am1[i]; a.bmap[i] = bm1[i]; }
        a.vec = b1 + l*FF; a.osplit = pfs;
        mma_gemm<<<dim3(32, 64), 256, SMEM_SZ>>>(a);

        // FFN2: g_fs x w2_split + bias -> y. M=1024, K'=12288
        a = GArgs{};
        a.A = pfs; a.B = pwf2 + (size_t)l*1024*8192;
        a.lda = 8192; a.ldb = 8192;
        a.k1sh = 12; a.nst = 384; a.mode = 3;
        for (int i = 0; i < 6; i++){ a.amap[i] = am1[i]; a.bmap[i] = bm1[i]; }
        a.vec = b2 + l*HH; a.out0 = py;
        mma_gemm<<<dim3(8, 64), 256, SMEM_SZ>>>(a);

        float* lnout = (l == LL-1) ? out : ph;
        ln_kernel<<<NN, 256>>>(ph, py, nullptr, fnb + l*HH, lnout, phs);
    }
}

// round 14
// speedup vs baseline: 1.2147x; 1.1154x over previous
#include <cuda_runtime.h>
#include <cuda_bf16.h>
#include <cstdint>

#define BB 4
#define SS 2048
#define HH 1024
#define LL 4
#define FF 4096
#define NN (BB*SS)
#define NCHUNK 32
#define CLEN (SS/NCHUNK)

// GEMM tiling (R10 shape): BM=128, BN=128, BK=32, 256 thr (2x4 warps, 64x32 warp tile), 4 stages
#define PITCH 80                      // 64B data + 16B pad per 32-bf16 row
#define A_BYTES (128*PITCH)           // 10240
#define STG_BYTES (2*A_BYTES)         // 20480 (A + B)
#define NSTAGE 4
#define SMEM_SZ (NSTAGE*STG_BYTES)    // 81920

// ---------------- scratch ----------------
__device__ __align__(256) float g_h  [(size_t)NN*HH];
__device__ __align__(256) float g_tre[(size_t)NN*HH];
__device__ __align__(256) float g_tim[(size_t)NN*HH];
__device__ __align__(256) float g_y  [(size_t)NN*HH];
__device__ float2 g_carry[BB*NCHUNK*HH];
__device__ __align__(256) __nv_bfloat16 g_hs[(size_t)NN*2*HH];   // h split [hi|lo]
__device__ __align__(256) __nv_bfloat16 g_sp[(size_t)NN*4*HH];   // scan out [re_hi|re_lo|im_hi|im_lo]
__device__ __align__(256) __nv_bfloat16 g_fs[(size_t)NN*2*FF];   // gelu out [hi|lo]
__device__ __align__(256) __nv_bfloat16 g_wbu[(size_t)LL*2048*2048];
__device__ __align__(256) __nv_bfloat16 g_wy [(size_t)LL*1024*4096];
__device__ __align__(256) __nv_bfloat16 g_wf1[(size_t)LL*4096*2048];
__device__ __align__(256) __nv_bfloat16 g_wf2[(size_t)LL*1024*8192];

// ---------------- helpers ----------------
__device__ __forceinline__ uint32_t smem_u32(const void* p){
    uint32_t a;
    asm("{ .reg .u64 t; cvta.to.shared.u64 t, %1; cvt.u32.u64 %0, t; }" : "=r"(a) : "l"(p));
    return a;
}
#define CPA_COMMIT() asm volatile("cp.async.commit_group;" ::: "memory")
#define CPA_WAIT2()  asm volatile("cp.async.wait_group 2;" ::: "memory")
__device__ __forceinline__ void cpa16(uint32_t d, const void* s){
    asm volatile("cp.async.cg.shared.global [%0], [%1], 16;" :: "r"(d), "l"(s));
}
__device__ __forceinline__ void ldsm4(uint32_t& r0, uint32_t& r1, uint32_t& r2, uint32_t& r3, uint32_t a){
    asm volatile("ldmatrix.sync.aligned.m8n8.x4.shared.b16 {%0,%1,%2,%3}, [%4];"
        : "=r"(r0), "=r"(r1), "=r"(r2), "=r"(r3) : "r"(a));
}
__device__ __forceinline__ void mma16816(float* d, const uint32_t* a, const uint32_t* b){
    asm volatile("mma.sync.aligned.m16n8k16.row.col.f32.bf16.bf16.f32 "
        "{%0,%1,%2,%3}, {%4,%5,%6,%7}, {%8,%9}, {%0,%1,%2,%3};"
        : "+f"(d[0]), "+f"(d[1]), "+f"(d[2]), "+f"(d[3])
        : "r"(a[0]), "r"(a[1]), "r"(a[2]), "r"(a[3]), "r"(b[0]), "r"(b[1]));
}
__device__ __forceinline__ void split2(float x, __nv_bfloat16& hi, __nv_bfloat16& lo){
    hi = __float2bfloat16(x);
    lo = __float2bfloat16(x - __bfloat162float(hi));
}
__device__ __forceinline__ void split4_store(float4 v, __nv_bfloat16* bhi, __nv_bfloat16* blo){
    float xs[4] = {v.x, v.y, v.z, v.w};
    uint32_t h[4], l[4];
    #pragma unroll
    for (int i = 0; i < 4; i++){
        __nv_bfloat16 hb, lb; split2(xs[i], hb, lb);
        h[i] = (uint32_t)__bfloat16_as_ushort(hb);
        l[i] = (uint32_t)__bfloat16_as_ushort(lb);
    }
    *(uint2*)bhi = make_uint2(h[0] | (h[1]<<16), h[2] | (h[3]<<16));
    *(uint2*)blo = make_uint2(l[0] | (l[1]<<16), l[2] | (l[3]<<16));
}

// ---------------- embedding (+ split) ----------------
__global__ void embed_kernel(const int* __restrict__ ids, const float* __restrict__ we,
                             const float* __restrict__ pe, float* __restrict__ out,
                             __nv_bfloat16* __restrict__ outs)
{
    int e = blockIdx.x * blockDim.x + threadIdx.x;
    int n  = e >> 8;
    int hq = (e & 255) << 2;
    int s  = n & (SS - 1);
    int id = ids[n];
    float4 w = *(const float4*)(we + (size_t)id * HH + hq);
    float4 p = *(const float4*)(pe + (size_t)s  * HH + hq);
    float4 v = make_float4(w.x+p.x, w.y+p.y, w.z+p.z, w.w+p.w);
    *(float4*)(out + (size_t)n * HH + hq) = v;
    split4_store(v, outs + (size_t)n*2*HH + hq, outs + (size_t)n*2*HH + HH + hq);
}

// ---------------- batched weight splitter: ALL 24 jobs in one launch ----------------
__global__ void split_all(const float* __restrict__ Bre, const float* __restrict__ Bim,
                          const float* __restrict__ Cre, const float* __restrict__ Cim,
                          const float* __restrict__ w1,  const float* __restrict__ w2,
                          __nv_bfloat16* __restrict__ wbu, __nv_bfloat16* __restrict__ wy,
                          __nv_bfloat16* __restrict__ wf1, __nv_bfloat16* __restrict__ wf2)
{
    const int blk = blockIdx.x;
    const int l   = blockIdx.y;
    const size_t hh = (size_t)HH*HH;
    const float* src; __nv_bfloat16* dst;
    int ksh; long ldo, coff; float sgn; int idx0;
    if (blk < 1024){        src = Bre + l*hh; dst = wbu + (size_t)l*2048*2048;
                            ksh = 10; ldo = 2048; coff = 0;    sgn = 1.f; idx0 = blk; }
    else if (blk < 2048){   src = Bim + l*hh; dst = wbu + (size_t)l*2048*2048 + 1024L*2048;
                            ksh = 10; ldo = 2048; coff = 0;    sgn = 1.f; idx0 = blk - 1024; }
    else if (blk < 3072){   src = Cre + l*hh; dst = wy  + (size_t)l*1024*4096;
                            ksh = 10; ldo = 4096; coff = 0;    sgn = 1.f; idx0 = blk - 2048; }
    else if (blk < 4096){   src = Cim + l*hh; dst = wy  + (size_t)l*1024*4096;
                            ksh = 10; ldo = 4096; coff = 2048; sgn = -1.f; idx0 = blk - 3072; }
    else if (blk < 8192){   src = w1 + (size_t)l*FF*HH; dst = wf1 + (size_t)l*4096*2048;
                            ksh = 10; ldo = 2048; coff = 0;    sgn = 1.f; idx0 = blk - 4096; }
    else{                   src = w2 + (size_t)l*HH*FF; dst = wf2 + (size_t)l*1024*8192;
                            ksh = 12; ldo = 8192; coff = 0;    sgn = 1.f; idx0 = blk - 8192; }
    long e = ((long)idx0 * 256 + threadIdx.x) * 4;
    long K = 1L << ksh;
    long r = e >> ksh;
    long c = e & (K - 1);
    float4 x = *(const float4*)(src + e);
    x.x *= sgn; x.y *= sgn; x.z *= sgn; x.w *= sgn;
    split4_store(x, dst + r*ldo + coff + c, dst + r*ldo + coff + K + c);
}

// ---------------- mma.sync GEMM: C[rows x M cols] = A'[.,K'] @ B'[M,K']^T ----------------
struct GArgs {
    const __nv_bfloat16* A; const __nv_bfloat16* B;
    long lda, ldb;
    int k1sh, nst, mode, nbase; // mode 0=BU(gamma) 1=Y 2=F1(gelu+split) 3=F2(bias)
    int amap[6], bmap[6];
    const float* vec;
    float* out0; float* out1;
    __nv_bfloat16* osplit;
};

__global__ __launch_bounds__(256, 2) void mma_gemm(const __grid_constant__ GArgs g)
{
    extern __shared__ char sm[];
    __shared__ float tab[128];
    const uint32_t sbase = smem_u32(sm);
    const int tid = threadIdx.x, lane = tid & 31, wid = tid >> 5;
    const int n0 = g.nbase + blockIdx.y * 128;   // token rows
    const int m0 = blockIdx.x * 128;             // output cols

    if (tid < 128){
        if (g.mode == 0)
            tab[tid] = sqrtf(fmaxf(1.f - expf(-2.f * expf(g.vec[(m0 + tid) & (HH-1)])), 0.f));
        else if (g.mode >= 2)
            tab[tid] = g.vec[m0 + tid];
    }

    // cp.async mapping: thread -> row tid>>1, chunk pair (tid&1)*2 (32B per thread per tile)
    const int arow = tid >> 1;
    const int ac0  = (tid & 1) * 2;
    const __nv_bfloat16* gA = g.A + (size_t)(n0 + arow) * g.lda + ac0*8;
    const __nv_bfloat16* gB = g.B + (size_t)(m0 + arow) * g.ldb + ac0*8;
    const uint32_t dA = (uint32_t)(arow*PITCH + ac0*16);
    const uint32_t dB = (uint32_t)(A_BYTES + arow*PITCH + ac0*16);

    const int k1m = (1 << g.k1sh) - 1;
    auto load_stage = [&](int s){
        int k0 = s << 5;                          // BK=32 elements
        int seg = k0 >> g.k1sh;
        long ka = ((long)g.amap[seg] << g.k1sh) + (k0 & k1m);
        long kb = ((long)g.bmap[seg] << g.k1sh) + (k0 & k1m);
        uint32_t base = sbase + (uint32_t)(s & (NSTAGE-1)) * STG_BYTES;
        cpa16(base + dA,      gA + ka);
        cpa16(base + dA + 16, gA + ka + 8);
        cpa16(base + dB,      gB + kb);
        cpa16(base + dB + 16, gB + kb + 8);
        CPA_COMMIT();
    };

    // warp layout: 2 (M) x 4 (N); warp tile 64x32
    const int warp_m = wid & 1, warp_n = wid >> 1;
    const int ra = (lane & 7) + (((lane >> 3) & 1) << 3);
    const int ca = (lane >> 4) * 16;
    const int rb = (lane & 7) + (((lane >> 4) & 1) << 3);
    const int cb = ((lane >> 3) & 1) * 16;
    uint32_t aoff[4], boff[2];
    #pragma unroll
    for (int mt = 0; mt < 4; mt++)
        aoff[mt] = (uint32_t)((warp_m*64 + mt*16 + ra) * PITCH + ca);
    #pragma unroll
    for (int ntp = 0; ntp < 2; ntp++)
        boff[ntp] = (uint32_t)(A_BYTES + (warp_n*32 + ntp*16 + rb) * PITCH + cb);

    float acc[4][4][4];
    #pragma unroll
    for (int i = 0; i < 4; i++)
        #pragma unroll
        for (int j = 0; j < 4; j++)
            #pragma unroll
            for (int r = 0; r < 4; r++) acc[i][j][r] = 0.f;

    for (int s = 0; s < NSTAGE-1; s++) load_stage(s);

    const int nst = g.nst;
    for (int i = 0; i < nst; i++){
        CPA_WAIT2();
        __syncthreads();
        uint32_t sb0 = sbase + (uint32_t)(i & (NSTAGE-1)) * STG_BYTES;
        #pragma unroll
        for (int s = 0; s < 2; s++){             // two k16 steps per stage
            uint32_t a[4][4], b[4][2];
            #pragma unroll
            for (int mt = 0; mt < 4; mt++)
                ldsm4(a[mt][0], a[mt][1], a[mt][2], a[mt][3], sb0 + aoff[mt] + s*32);
            #pragma unroll
            for (int ntp = 0; ntp < 2; ntp++){
                uint32_t r0, r1, r2, r3;
                ldsm4(r0, r1, r2, r3, sb0 + boff[ntp] + s*32);
                b[2*ntp][0] = r0;   b[2*ntp][1] = r1;
                b[2*ntp+1][0] = r2; b[2*ntp+1][1] = r3;
            }
            #pragma unroll
            for (int mt = 0; mt < 4; mt++)
                #pragma unroll
                for (int nt = 0; nt < 4; nt++)
                    mma16816(acc[mt][nt], a[mt], b[nt]);
        }
        int j = i + NSTAGE - 1;
        if (j < nst) load_stage(j);
        else CPA_COMMIT();
    }

    // epilogue
    const int rbase = n0 + warp_m*64 + (lane >> 2);
    const int cbase = warp_n*32 + (lane & 3)*2;
    #pragma unroll
    for (int mt = 0; mt < 4; mt++){
        #pragma unroll
        for (int nt = 0; nt < 4; nt++){
            int cl = cbase + nt*8;
            int col = m0 + cl;
            #pragma unroll
            for (int h = 0; h < 2; h++){
                int row = rbase + mt*16 + h*8;
                float v0 = acc[mt][nt][h*2+0];
                float v1 = acc[mt][nt][h*2+1];
                if (g.mode == 0){
                    float* dst = (col < HH) ? g.out0 : g.out1;
                    int cm = col & (HH-1);
                    *(float2*)(dst + (size_t)row*HH + cm) =
                        make_float2(v0 * tab[cl], v1 * tab[cl+1]);
                } else if (g.mode == 1){
                    *(float2*)(g.out0 + (size_t)row*HH + col) = make_float2(v0, v1);
                } else if (g.mode == 2){
                    float x0 = v0 + tab[cl], x1 = v1 + tab[cl+1];
                    x0 = x0 * normcdff(x0);                 // exact GELU
                    x1 = x1 * normcdff(x1);
                    __nv_bfloat16 h0, l0, h1, l1;
                    split2(x0, h0, l0); split2(x1, h1, l1);
                    uint32_t hw = (uint32_t)__bfloat16_as_ushort(h0) | ((uint32_t)__bfloat16_as_ushort(h1) << 16);
                    uint32_t lw = (uint32_t)__bfloat16_as_ushort(l0) | ((uint32_t)__bfloat16_as_ushort(l1) << 16);
                    size_t bh = (size_t)row * (2*FF) + col;
                    *(uint32_t*)(g.osplit + bh)      = hw;
                    *(uint32_t*)(g.osplit + bh + FF) = lw;
                } else {
                    *(float2*)(g.out0 + (size_t)row*HH + col) =
                        make_float2(v0 + tab[cl], v1 + tab[cl+1]);
                }
            }
        }
    }
}

// ---------------- chunked complex scan (per-stream: 2 batches) ----------------
__device__ __forceinline__ void lam_of(const float* nul, const float* thl, int u,
                                       float& lre, float& lim)
{
    float r   = expf(-expf(nul[u]));
    float ang = expf(thl[u]);
    lre = r * cosf(ang);
    lim = r * sinf(ang);
}

// pass1: per-chunk inclusive local carry only (no writeback)
__global__ void scan_pass1(const float* __restrict__ nul, const float* __restrict__ thl,
                           const float* __restrict__ tre, const float* __restrict__ tim,
                           float2* __restrict__ carry, int b0)
{
    int t = blockIdx.x * blockDim.x + threadIdx.x;   // 2*NCHUNK*HH threads
    int u = t & (HH - 1);
    int rest = t >> 10;
    int c = rest & (NCHUNK - 1);
    int b = b0 + (rest >> 5);
    float lre, lim; lam_of(nul, thl, u, lre, lim);
    size_t base = ((size_t)b * SS + (size_t)c * CLEN) * HH + u;
    float sre = 0.f, sim = 0.f;
    #pragma unroll 4
    for (int i = 0; i < CLEN; i++) {
        size_t ix = base + (size_t)i * HH;
        float xr = tre[ix], xi = tim[ix];
        float nr = fmaf(lre, sre, fmaf(-lim, sim, xr));
        float ni = fmaf(lre, sim, fmaf( lim, sre, xi));
        sre = nr; sim = ni;
    }
    carry[(b * NCHUNK + c) * HH + u] = make_float2(sre, sim);
}

// pass3 (pass2 folded in): exclusive chunk carry via Horner over chunk carries,
// redo local scan, emit bf16 splits
__global__ void scan_pass3(const float* __restrict__ nul, const float* __restrict__ thl,
                           const float* __restrict__ tre, const float* __restrict__ tim,
                           const float2* __restrict__ carry, __nv_bfloat16* __restrict__ sp,
                           int b0)
{
    int t = blockIdx.x * blockDim.x + threadIdx.x;
    int u = t & (HH - 1);
    int rest = t >> 10;
    int c = rest & (NCHUNK - 1);
    int b = b0 + (rest >> 5);
    float lre, lim; lam_of(nul, thl, u, lre, lim);
    // lamC = lam^CLEN
    float pr = 1.f, pi = 0.f;
    #pragma unroll
    for (int i = 0; i < CLEN; i++) {
        float nr = pr * lre - pi * lim;
        float ni = pr * lim + pi * lre;
        pr = nr; pi = ni;
    }
    // exclusive carry (Horner, j ascending)
    float ccr = 0.f, cci = 0.f;
    for (int j = 0; j < c; j++) {
        float2 f = carry[(b * NCHUNK + j) * HH + u];
        float nr = fmaf(pr, ccr, fmaf(-pi, cci, f.x));
        float ni = fmaf(pr, cci, fmaf( pi, ccr, f.y));
        ccr = nr; cci = ni;
    }
    size_t base = ((size_t)b * SS + (size_t)c * CLEN) * HH + u;
    size_t nbase = (size_t)b * SS + (size_t)c * CLEN;
    float sre = ccr, sim = cci;
    for (int i = 0; i < CLEN; i++) {
        size_t ix = base + (size_t)i * HH;
        float xr = tre[ix], xi = tim[ix];
        float nr = fmaf(lre, sre, fmaf(-lim, sim, xr));
        float ni = fmaf(lre, sim, fmaf( lim, sre, xi));
        sre = nr; sim = ni;
        size_t ro = (nbase + i) * (4*HH) + u;
        __nv_bfloat16 h1, l1, h2, l2;
        split2(sre, h1, l1); split2(sim, h2, l2);
        sp[ro]        = h1;
        sp[ro + HH]   = l1;
        sp[ro + 2*HH] = h2;
        sp[ro + 3*HH] = l2;
    }
}

// ---------------- fused residual + RMS-LN (+ split output) ----------------
__global__ void ln_kernel(const float* __restrict__ h, const float* __restrict__ y,
                          const float* __restrict__ Dl, const float* __restrict__ bias,
                          float* __restrict__ out, __nv_bfloat16* __restrict__ osplit,
                          int nb)
{
    int n = nb + blockIdx.x;
    int t = threadIdx.x;
    size_t idx = (size_t)n * HH + (t << 2);
    float4 hv = *(const float4*)(h + idx);
    float4 yv = *(const float4*)(y + idx);
    float4 z;
    if (Dl) {
        float4 dv = *(const float4*)(Dl + (t << 2));
        z.x = fmaf(hv.x, 1.f + dv.x, yv.x);
        z.y = fmaf(hv.y, 1.f + dv.y, yv.y);
        z.z = fmaf(hv.z, 1.f + dv.z, yv.z);
        z.w = fmaf(hv.w, 1.f + dv.w, yv.w);
    } else {
        z.x = hv.x + yv.x; z.y = hv.y + yv.y; z.z = hv.z + yv.z; z.w = hv.w + yv.w;
    }
    float s = z.x*z.x + z.y*z.y + z.z*z.z + z.w*z.w;
    #pragma unroll
    for (int o = 16; o; o >>= 1) s += __shfl_xor_sync(0xffffffffu, s, o);
    __shared__ float red[8];
    if ((t & 31) == 0) red[t >> 5] = s;
    __syncthreads();
    float tot = red[0]+red[1]+red[2]+red[3]+red[4]+red[5]+red[6]+red[7];
    float inv = rsqrtf(tot * (1.f / (float)HH) + 1e-12f);
    float4 bv = *(const float4*)(bias + (t << 2));
    float4 o4 = make_float4(fmaf(z.x, inv, bv.x), fmaf(z.y, inv, bv.y),
                            fmaf(z.z, inv, bv.z), fmaf(z.w, inv, bv.w));
    *(float4*)(out + idx) = o4;
    split4_store(o4, osplit + (size_t)n*2*HH + (t<<2),
                     osplit + (size_t)n*2*HH + HH + (t<<2));
}

// ---------------- launch ----------------
extern "C" void kernel_launch(void* const* d_in, const int* in_sizes, int n_in,
                              void* d_out, int out_size)
{
    const int*   ids = (const int*)  d_in[0];
    const float* we  = (const float*)d_in[1];
    const float* pe  = (const float*)d_in[2];
    const float* nu  = (const float*)d_in[3];
    const float* th  = (const float*)d_in[4];
    const float* Bre = (const float*)d_in[5];
    const float* Bim = (const float*)d_in[6];
    const float* Cre = (const float*)d_in[7];
    const float* Cim = (const float*)d_in[8];
    const float* Dp  = (const float*)d_in[9];
    const float* rnb = (const float*)d_in[10];
    const float* w1  = (const float*)d_in[11];
    const float* b1  = (const float*)d_in[12];
    const float* w2  = (const float*)d_in[13];
    const float* b2  = (const float*)d_in[14];
    const float* fnb = (const float*)d_in[15];
    float* out = (float*)d_out;

    float *ph, *ptre, *ptim, *py; float2* pc;
    __nv_bfloat16 *phs, *psp, *pfs, *pwbu, *pwy, *pwf1, *pwf2;
    cudaGetSymbolAddress((void**)&ph,   g_h);
    cudaGetSymbolAddress((void**)&ptre, g_tre);
    cudaGetSymbolAddress((void**)&ptim, g_tim);
    cudaGetSymbolAddress((void**)&py,   g_y);
    cudaGetSymbolAddress((void**)&pc,   g_carry);
    cudaGetSymbolAddress((void**)&phs,  g_hs);
    cudaGetSymbolAddress((void**)&psp,  g_sp);
    cudaGetSymbolAddress((void**)&pfs,  g_fs);
    cudaGetSymbolAddress((void**)&pwbu, g_wbu);
    cudaGetSymbolAddress((void**)&pwy,  g_wy);
    cudaGetSymbolAddress((void**)&pwf1, g_wf1);
    cudaGetSymbolAddress((void**)&pwf2, g_wf2);

    cudaFuncSetAttribute(mma_gemm, cudaFuncAttributeMaxDynamicSharedMemorySize, SMEM_SZ);

    // fork a second stream (capture-legal event fork/join off the default stream)
    cudaStream_t s1;
    cudaStreamCreateWithFlags(&s1, cudaStreamNonBlocking);
    cudaEvent_t ef, ej;
    cudaEventCreateWithFlags(&ef, cudaEventDisableTiming);
    cudaEventCreateWithFlags(&ej, cudaEventDisableTiming);

    // prelude on default stream
    split_all<<<dim3(12288, LL), 256>>>(Bre, Bim, Cre, Cim, w1, w2, pwbu, pwy, pwf1, pwf2);
    embed_kernel<<<(size_t)NN*HH/4/256, 256>>>(ids, we, pe, ph, phs);
    cudaEventRecord(ef, 0);
    cudaStreamWaitEvent(s1, ef, 0);

    int am1[6] = {0,0,1,0,0,0}, bm1[6] = {0,1,0,0,0,0};          // 3-seg: hihi, hilo, lohi
    int am2[6] = {0,0,1,2,2,3}, bm2[6] = {0,1,0,2,3,2};          // 6-seg complex

    cudaStream_t strm[2] = {0, s1};

    for (int l = 0; l < LL; l++) {
        const float* nul = nu + l*HH;
        const float* thl = th + l*HH;

        for (int si = 0; si < 2; si++) {
            cudaStream_t st = strm[si];
            const int nb = si * (NN/2);          // row base: 0 or 4096
            const int b0 = si * 2;               // batch base: 0 or 2

            // BU: [h_hi|h_lo] x [Bre;Bim] -> tre/tim (gamma fused). M=2048, K'=3072
            GArgs a = {};
            a.A = phs; a.B = pwbu + (size_t)l*2048*2048;
            a.lda = 2048; a.ldb = 2048;
            a.k1sh = 10; a.nst = 96; a.mode = 0; a.nbase = nb;
            for (int i = 0; i < 6; i++){ a.amap[i] = am1[i]; a.bmap[i] = bm1[i]; }
            a.vec = nul; a.out0 = ptre; a.out1 = ptim;
            mma_gemm<<<dim3(16, 32), 256, SMEM_SZ, st>>>(a);

            scan_pass1<<<2*NCHUNK*HH/256, 256, 0, st>>>(nul, thl, ptre, ptim, pc, b0);
            scan_pass3<<<2*NCHUNK*HH/256, 256, 0, st>>>(nul, thl, ptre, ptim, pc, psp, b0);

            // Y: [re_hi|re_lo|im_hi|im_lo] x [Cre|-Cim] -> y. M=1024, K'=6144
            a = GArgs{};
            a.A = psp; a.B = pwy + (size_t)l*1024*4096;
            a.lda = 4096; a.ldb = 4096;
            a.k1sh = 10; a.nst = 192; a.mode = 1; a.nbase = nb;
            for (int i = 0; i < 6; i++){ a.amap[i] = am2[i]; a.bmap[i] = bm2[i]; }
            a.out0 = py;
            mma_gemm<<<dim3(8, 32), 256, SMEM_SZ, st>>>(a);

            ln_kernel<<<NN/2, 256, 0, st>>>(ph, py, Dp + l*HH, rnb + l*HH, ph, phs, nb);

            // FFN1: h_split x w1_split -> gelu -> g_fs. M=4096, K'=3072
            a = GArgs{};
            a.A = phs; a.B = pwf1 + (size_t)l*4096*2048;
            a.lda = 2048; a.ldb = 2048;
            a.k1sh = 10; a.nst = 96; a.mode = 2; a.nbase = nb;
            for (int i = 0; i < 6; i++){ a.amap[i] = am1[i]; a.bmap[i] = bm1[i]; }
            a.vec = b1 + l*FF; a.osplit = pfs;
            mma_gemm<<<dim3(32, 32), 256, SMEM_SZ, st>>>(a);

            // FFN2: g_fs x w2_split + bias -> y. M=1024, K'=12288
            a = GArgs{};
            a.A = pfs; a.B = pwf2 + (size_t)l*1024*8192;
            a.lda = 8192; a.ldb = 8192;
            a.k1sh = 12; a.nst = 384; a.mode = 3; a.nbase = nb;
            for (int i = 0; i < 6; i++){ a.amap[i] = am1[i]; a.bmap[i] = bm1[i]; }
            a.vec = b2 + l*HH; a.out0 = py;
            mma_gemm<<<dim3(8, 32), 256, SMEM_SZ, st>>>(a);

            float* lnout = (l == LL-1) ? out : ph;
            ln_kernel<<<NN/2, 256, 0, st>>>(ph, py, nullptr, fnb + l*HH, lnout, phs, nb);
        }
    }

    // join
    cudaEventRecord(ej, s1);
    cudaStreamWaitEvent(0, ej, 0);
}

// round 16
// speedup vs baseline: 1.2273x; 1.0104x over previous
#include <cuda_runtime.h>
#include <cuda_bf16.h>
#include <cstdint>

#define BB 4
#define SS 2048
#define HH 1024
#define LL 4
#define FF 4096
#define NN (BB*SS)
#define NCHUNK 32
#define CLEN (SS/NCHUNK)

// GEMM tiling (R10 shape): BM=128, BN=128, BK=32, 256 thr (2x4 warps, 64x32 warp tile), 4 stages
#define PITCH 80                      // 64B data + 16B pad per 32-bf16 row
#define A_BYTES (128*PITCH)           // 10240
#define STG_BYTES (2*A_BYTES)         // 20480 (A + B)
#define NSTAGE 4
#define SMEM_SZ (NSTAGE*STG_BYTES)    // 81920

// ---------------- scratch ----------------
__device__ __align__(256) float g_h  [(size_t)NN*HH];
__device__ __align__(256) float g_tre[(size_t)NN*HH];
__device__ __align__(256) float g_tim[(size_t)NN*HH];
__device__ __align__(256) float g_y  [(size_t)NN*HH];
__device__ float2 g_carry[BB*NCHUNK*HH];
__device__ __align__(256) __nv_bfloat16 g_hs[(size_t)NN*2*HH];   // h split [hi|lo]
__device__ __align__(256) __nv_bfloat16 g_sp[(size_t)NN*4*HH];   // scan out [re_hi|re_lo|im_hi|im_lo]
__device__ __align__(256) __nv_bfloat16 g_fs[(size_t)NN*2*FF];   // gelu out [hi|lo]
__device__ __align__(256) __nv_bfloat16 g_wbu[(size_t)LL*2048*2048];
__device__ __align__(256) __nv_bfloat16 g_wy [(size_t)LL*1024*4096];
__device__ __align__(256) __nv_bfloat16 g_wf1[(size_t)LL*4096*2048];
__device__ __align__(256) __nv_bfloat16 g_wf2[(size_t)LL*1024*8192];

// ---------------- helpers ----------------
__device__ __forceinline__ uint32_t smem_u32(const void* p){
    uint32_t a;
    asm("{ .reg .u64 t; cvta.to.shared.u64 t, %1; cvt.u32.u64 %0, t; }" : "=r"(a) : "l"(p));
    return a;
}
#define CPA_COMMIT() asm volatile("cp.async.commit_group;" ::: "memory")
#define CPA_WAIT2()  asm volatile("cp.async.wait_group 2;" ::: "memory")
__device__ __forceinline__ void cpa16(uint32_t d, const void* s){
    asm volatile("cp.async.cg.shared.global [%0], [%1], 16;" :: "r"(d), "l"(s));
}
__device__ __forceinline__ void ldsm4(uint32_t& r0, uint32_t& r1, uint32_t& r2, uint32_t& r3, uint32_t a){
    asm volatile("ldmatrix.sync.aligned.m8n8.x4.shared.b16 {%0,%1,%2,%3}, [%4];"
        : "=r"(r0), "=r"(r1), "=r"(r2), "=r"(r3) : "r"(a));
}
__device__ __forceinline__ void mma16816(float* d, const uint32_t* a, const uint32_t* b){
    asm volatile("mma.sync.aligned.m16n8k16.row.col.f32.bf16.bf16.f32 "
        "{%0,%1,%2,%3}, {%4,%5,%6,%7}, {%8,%9}, {%0,%1,%2,%3};"
        : "+f"(d[0]), "+f"(d[1]), "+f"(d[2]), "+f"(d[3])
        : "r"(a[0]), "r"(a[1]), "r"(a[2]), "r"(a[3]), "r"(b[0]), "r"(b[1]));
}
__device__ __forceinline__ void split2(float x, __nv_bfloat16& hi, __nv_bfloat16& lo){
    hi = __float2bfloat16(x);
    lo = __float2bfloat16(x - __bfloat162float(hi));
}
__device__ __forceinline__ void split4_store(float4 v, __nv_bfloat16* bhi, __nv_bfloat16* blo){
    float xs[4] = {v.x, v.y, v.z, v.w};
    uint32_t h[4], l[4];
    #pragma unroll
    for (int i = 0; i < 4; i++){
        __nv_bfloat16 hb, lb; split2(xs[i], hb, lb);
        h[i] = (uint32_t)__bfloat16_as_ushort(hb);
        l[i] = (uint32_t)__bfloat16_as_ushort(lb);
    }
    *(uint2*)bhi = make_uint2(h[0] | (h[1]<<16), h[2] | (h[3]<<16));
    *(uint2*)blo = make_uint2(l[0] | (l[1]<<16), l[2] | (l[3]<<16));
}

// ---------------- embedding (+ split) ----------------
__global__ void embed_kernel(const int* __restrict__ ids, const float* __restrict__ we,
                             const float* __restrict__ pe, float* __restrict__ out,
                             __nv_bfloat16* __restrict__ outs)
{
    int e = blockIdx.x * blockDim.x + threadIdx.x;
    int n  = e >> 8;
    int hq = (e & 255) << 2;
    int s  = n & (SS - 1);
    int id = ids[n];
    float4 w = *(const float4*)(we + (size_t)id * HH + hq);
    float4 p = *(const float4*)(pe + (size_t)s  * HH + hq);
    float4 v = make_float4(w.x+p.x, w.y+p.y, w.z+p.z, w.w+p.w);
    *(float4*)(out + (size_t)n * HH + hq) = v;
    split4_store(v, outs + (size_t)n*2*HH + hq, outs + (size_t)n*2*HH + HH + hq);
}

// ---------------- batched weight splitter: ALL 24 jobs in one launch ----------------
__global__ void split_all(const float* __restrict__ Bre, const float* __restrict__ Bim,
                          const float* __restrict__ Cre, const float* __restrict__ Cim,
                          const float* __restrict__ w1,  const float* __restrict__ w2,
                          __nv_bfloat16* __restrict__ wbu, __nv_bfloat16* __restrict__ wy,
                          __nv_bfloat16* __restrict__ wf1, __nv_bfloat16* __restrict__ wf2)
{
    const int blk = blockIdx.x;
    const int l   = blockIdx.y;
    const size_t hh = (size_t)HH*HH;
    const float* src; __nv_bfloat16* dst;
    int ksh; long ldo, coff; float sgn; int idx0;
    if (blk < 1024){        src = Bre + l*hh; dst = wbu + (size_t)l*2048*2048;
                            ksh = 10; ldo = 2048; coff = 0;    sgn = 1.f; idx0 = blk; }
    else if (blk < 2048){   src = Bim + l*hh; dst = wbu + (size_t)l*2048*2048 + 1024L*2048;
                            ksh = 10; ldo = 2048; coff = 0;    sgn = 1.f; idx0 = blk - 1024; }
    else if (blk < 3072){   src = Cre + l*hh; dst = wy  + (size_t)l*1024*4096;
                            ksh = 10; ldo = 4096; coff = 0;    sgn = 1.f; idx0 = blk - 2048; }
    else if (blk < 4096){   src = Cim + l*hh; dst = wy  + (size_t)l*1024*4096;
                            ksh = 10; ldo = 4096; coff = 2048; sgn = -1.f; idx0 = blk - 3072; }
    else if (blk < 8192){   src = w1 + (size_t)l*FF*HH; dst = wf1 + (size_t)l*4096*2048;
                            ksh = 10; ldo = 2048; coff = 0;    sgn = 1.f; idx0 = blk - 4096; }
    else{                   src = w2 + (size_t)l*HH*FF; dst = wf2 + (size_t)l*1024*8192;
                            ksh = 12; ldo = 8192; coff = 0;    sgn = 1.f; idx0 = blk - 8192; }
    long e = ((long)idx0 * 256 + threadIdx.x) * 4;
    long K = 1L << ksh;
    long r = e >> ksh;
    long c = e & (K - 1);
    float4 x = *(const float4*)(src + e);
    x.x *= sgn; x.y *= sgn; x.z *= sgn; x.w *= sgn;
    split4_store(x, dst + r*ldo + coff + c, dst + r*ldo + coff + K + c);
}

// ---------------- mma.sync GEMM: C[rows x M cols] = A'[.,K'] @ B'[M,K']^T ----------------
struct GArgs {
    const __nv_bfloat16* A; const __nv_bfloat16* B;
    long lda, ldb;
    int k1sh, nst, mode, nbase; // mode 0=BU(gamma) 1=Y 2=F1(gelu+split) 3=F2(bias)
    int amap[6], bmap[6];
    const float* vec;
    float* out0; float* out1;
    __nv_bfloat16* osplit;
};

__global__ __launch_bounds__(256, 2) void mma_gemm(const __grid_constant__ GArgs g)
{
    extern __shared__ char sm[];
    __shared__ float tab[128];
    const uint32_t sbase = smem_u32(sm);
    const int tid = threadIdx.x, lane = tid & 31, wid = tid >> 5;
    const int n0 = g.nbase + blockIdx.y * 128;   // token rows
    const int m0 = blockIdx.x * 128;             // output cols

    if (tid < 128){
        if (g.mode == 0)
            tab[tid] = sqrtf(fmaxf(1.f - expf(-2.f * expf(g.vec[(m0 + tid) & (HH-1)])), 0.f));
        else if (g.mode >= 2)
            tab[tid] = g.vec[m0 + tid];
    }

    // cp.async mapping: thread -> row tid>>1, chunk pair (tid&1)*2 (32B per thread per tile)
    const int arow = tid >> 1;
    const int ac0  = (tid & 1) * 2;
    const __nv_bfloat16* gA = g.A + (size_t)(n0 + arow) * g.lda + ac0*8;
    const __nv_bfloat16* gB = g.B + (size_t)(m0 + arow) * g.ldb + ac0*8;
    const uint32_t dA = (uint32_t)(arow*PITCH + ac0*16);
    const uint32_t dB = (uint32_t)(A_BYTES + arow*PITCH + ac0*16);

    const int k1m = (1 << g.k1sh) - 1;
    auto load_stage = [&](int s){
        int k0 = s << 5;                          // BK=32 elements
        int seg = k0 >> g.k1sh;
        long ka = ((long)g.amap[seg] << g.k1sh) + (k0 & k1m);
        long kb = ((long)g.bmap[seg] << g.k1sh) + (k0 & k1m);
        uint32_t base = sbase + (uint32_t)(s & (NSTAGE-1)) * STG_BYTES;
        cpa16(base + dA,      gA + ka);
        cpa16(base + dA + 16, gA + ka + 8);
        cpa16(base + dB,      gB + kb);
        cpa16(base + dB + 16, gB + kb + 8);
        CPA_COMMIT();
    };

    // warp layout: 2 (M) x 4 (N); warp tile 64x32
    const int warp_m = wid & 1, warp_n = wid >> 1;
    const int ra = (lane & 7) + (((lane >> 3) & 1) << 3);
    const int ca = (lane >> 4) * 16;
    const int rb = (lane & 7) + (((lane >> 4) & 1) << 3);
    const int cb = ((lane >> 3) & 1) * 16;
    uint32_t aoff[4], boff[2];
    #pragma unroll
    for (int mt = 0; mt < 4; mt++)
        aoff[mt] = (uint32_t)((warp_m*64 + mt*16 + ra) * PITCH + ca);
    #pragma unroll
    for (int ntp = 0; ntp < 2; ntp++)
        boff[ntp] = (uint32_t)(A_BYTES + (warp_n*32 + ntp*16 + rb) * PITCH + cb);

    float acc[4][4][4];
    #pragma unroll
    for (int i = 0; i < 4; i++)
        #pragma unroll
        for (int j = 0; j < 4; j++)
            #pragma unroll
            for (int r = 0; r < 4; r++) acc[i][j][r] = 0.f;

    for (int s = 0; s < NSTAGE-1; s++) load_stage(s);

    const int nst = g.nst;
    for (int i = 0; i < nst; i++){
        CPA_WAIT2();
        __syncthreads();
        uint32_t sb0 = sbase + (uint32_t)(i & (NSTAGE-1)) * STG_BYTES;
        #pragma unroll
        for (int s = 0; s < 2; s++){             // two k16 steps per stage
            uint32_t a[4][4], b[4][2];
            #pragma unroll
            for (int mt = 0; mt < 4; mt++)
                ldsm4(a[mt][0], a[mt][1], a[mt][2], a[mt][3], sb0 + aoff[mt] + s*32);
            #pragma unroll
            for (int ntp = 0; ntp < 2; ntp++){
                uint32_t r0, r1, r2, r3;
                ldsm4(r0, r1, r2, r3, sb0 + boff[ntp] + s*32);
                b[2*ntp][0] = r0;   b[2*ntp][1] = r1;
                b[2*ntp+1][0] = r2; b[2*ntp+1][1] = r3;
            }
            #pragma unroll
            for (int mt = 0; mt < 4; mt++)
                #pragma unroll
                for (int nt = 0; nt < 4; nt++)
                    mma16816(acc[mt][nt], a[mt], b[nt]);
        }
        int j = i + NSTAGE - 1;
        if (j < nst) load_stage(j);
        else CPA_COMMIT();
    }

    // epilogue
    const int rbase = n0 + warp_m*64 + (lane >> 2);
    const int cbase = warp_n*32 + (lane & 3)*2;
    #pragma unroll
    for (int mt = 0; mt < 4; mt++){
        #pragma unroll
        for (int nt = 0; nt < 4; nt++){
            int cl = cbase + nt*8;
            int col = m0 + cl;
            #pragma unroll
            for (int h = 0; h < 2; h++){
                int row = rbase + mt*16 + h*8;
                float v0 = acc[mt][nt][h*2+0];
                float v1 = acc[mt][nt][h*2+1];
                if (g.mode == 0){
                    float* dst = (col < HH) ? g.out0 : g.out1;
                    int cm = col & (HH-1);
                    *(float2*)(dst + (size_t)row*HH + cm) =
                        make_float2(v0 * tab[cl], v1 * tab[cl+1]);
                } else if (g.mode == 1){
                    *(float2*)(g.out0 + (size_t)row*HH + col) = make_float2(v0, v1);
                } else if (g.mode == 2){
                    float x0 = v0 + tab[cl], x1 = v1 + tab[cl+1];
                    x0 = x0 * normcdff(x0);                 // exact GELU
                    x1 = x1 * normcdff(x1);
                    __nv_bfloat16 h0, l0, h1, l1;
                    split2(x0, h0, l0); split2(x1, h1, l1);
                    uint32_t hw = (uint32_t)__bfloat16_as_ushort(h0) | ((uint32_t)__bfloat16_as_ushort(h1) << 16);
                    uint32_t lw = (uint32_t)__bfloat16_as_ushort(l0) | ((uint32_t)__bfloat16_as_ushort(l1) << 16);
                    size_t bh = (size_t)row * (2*FF) + col;
                    *(uint32_t*)(g.osplit + bh)      = hw;
                    *(uint32_t*)(g.osplit + bh + FF) = lw;
                } else {
                    *(float2*)(g.out0 + (size_t)row*HH + col) =
                        make_float2(v0 + tab[cl], v1 + tab[cl+1]);
                }
            }
        }
    }
}

// ---------------- chunked complex scan (per-stream: 1 batch) ----------------
__device__ __forceinline__ void lam_of(const float* nul, const float* thl, int u,
                                       float& lre, float& lim)
{
    float r   = expf(-expf(nul[u]));
    float ang = expf(thl[u]);
    lre = r * cosf(ang);
    lim = r * sinf(ang);
}

// pass1: per-chunk inclusive local carry only (no writeback)
__global__ void scan_pass1(const float* __restrict__ nul, const float* __restrict__ thl,
                           const float* __restrict__ tre, const float* __restrict__ tim,
                           float2* __restrict__ carry, int b0)
{
    int t = blockIdx.x * blockDim.x + threadIdx.x;   // NCHUNK*HH threads
    int u = t & (HH - 1);
    int c = t >> 10;                                  // 0..NCHUNK-1
    int b = b0;
    float lre, lim; lam_of(nul, thl, u, lre, lim);
    size_t base = ((size_t)b * SS + (size_t)c * CLEN) * HH + u;
    float sre = 0.f, sim = 0.f;
    #pragma unroll 4
    for (int i = 0; i < CLEN; i++) {
        size_t ix = base + (size_t)i * HH;
        float xr = tre[ix], xi = tim[ix];
        float nr = fmaf(lre, sre, fmaf(-lim, sim, xr));
        float ni = fmaf(lre, sim, fmaf( lim, sre, xi));
        sre = nr; sim = ni;
    }
    carry[(b * NCHUNK + c) * HH + u] = make_float2(sre, sim);
}

// pass3 (pass2 folded in): exclusive chunk carry via Horner over chunk carries,
// redo local scan, emit bf16 splits
__global__ void scan_pass3(const float* __restrict__ nul, const float* __restrict__ thl,
                           const float* __restrict__ tre, const float* __restrict__ tim,
                           const float2* __restrict__ carry, __nv_bfloat16* __restrict__ sp,
                           int b0)
{
    int t = blockIdx.x * blockDim.x + threadIdx.x;
    int u = t & (HH - 1);
    int c = t >> 10;
    int b = b0;
    float lre, lim; lam_of(nul, thl, u, lre, lim);
    // lamC = lam^CLEN
    float pr = 1.f, pi = 0.f;
    #pragma unroll
    for (int i = 0; i < CLEN; i++) {
        float nr = pr * lre - pi * lim;
        float ni = pr * lim + pi * lre;
        pr = nr; pi = ni;
    }
    // exclusive carry (Horner, j ascending)
    float ccr = 0.f, cci = 0.f;
    for (int j = 0; j < c; j++) {
        float2 f = carry[(b * NCHUNK + j) * HH + u];
        float nr = fmaf(pr, ccr, fmaf(-pi, cci, f.x));
        float ni = fmaf(pr, cci, fmaf( pi, ccr, f.y));
        ccr = nr; cci = ni;
    }
    size_t base = ((size_t)b * SS + (size_t)c * CLEN) * HH + u;
    size_t nbase = (size_t)b * SS + (size_t)c * CLEN;
    float sre = ccr, sim = cci;
    for (int i = 0; i < CLEN; i++) {
        size_t ix = base + (size_t)i * HH;
        float xr = tre[ix], xi = tim[ix];
        float nr = fmaf(lre, sre, fmaf(-lim, sim, xr));
        float ni = fmaf(lre, sim, fmaf( lim, sre, xi));
        sre = nr; sim = ni;
        size_t ro = (nbase + i) * (4*HH) + u;
        __nv_bfloat16 h1, l1, h2, l2;
        split2(sre, h1, l1); split2(sim, h2, l2);
        sp[ro]        = h1;
        sp[ro + HH]   = l1;
        sp[ro + 2*HH] = h2;
        sp[ro + 3*HH] = l2;
    }
}

// ---------------- fused residual + RMS-LN (+ split output) ----------------
__global__ void ln_kernel(const float* __restrict__ h, const float* __restrict__ y,
                          const float* __restrict__ Dl, const float* __restrict__ bias,
                          float* __restrict__ out, __nv_bfloat16* __restrict__ osplit,
                          int nb)
{
    int n = nb + blockIdx.x;
    int t = threadIdx.x;
    size_t idx = (size_t)n * HH + (t << 2);
    float4 hv = *(const float4*)(h + idx);
    float4 yv = *(const float4*)(y + idx);
    float4 z;
    if (Dl) {
        float4 dv = *(const float4*)(Dl + (t << 2));
        z.x = fmaf(hv.x, 1.f + dv.x, yv.x);
        z.y = fmaf(hv.y, 1.f + dv.y, yv.y);
        z.z = fmaf(hv.z, 1.f + dv.z, yv.z);
        z.w = fmaf(hv.w, 1.f + dv.w, yv.w);
    } else {
        z.x = hv.x + yv.x; z.y = hv.y + yv.y; z.z = hv.z + yv.z; z.w = hv.w + yv.w;
    }
    float s = z.x*z.x + z.y*z.y + z.z*z.z + z.w*z.w;
    #pragma unroll
    for (int o = 16; o; o >>= 1) s += __shfl_xor_sync(0xffffffffu, s, o);
    __shared__ float red[8];
    if ((t & 31) == 0) red[t >> 5] = s;
    __syncthreads();
    float tot = red[0]+red[1]+red[2]+red[3]+red[4]+red[5]+red[6]+red[7];
    float inv = rsqrtf(tot * (1.f / (float)HH) + 1e-12f);
    float4 bv = *(const float4*)(bias + (t << 2));
    float4 o4 = make_float4(fmaf(z.x, inv, bv.x), fmaf(z.y, inv, bv.y),
                            fmaf(z.z, inv, bv.z), fmaf(z.w, inv, bv.w));
    *(float4*)(out + idx) = o4;
    split4_store(o4, osplit + (size_t)n*2*HH + (t<<2),
                     osplit + (size_t)n*2*HH + HH + (t<<2));
}

// ---------------- launch ----------------
extern "C" void kernel_launch(void* const* d_in, const int* in_sizes, int n_in,
                              void* d_out, int out_size)
{
    const int*   ids = (const int*)  d_in[0];
    const float* we  = (const float*)d_in[1];
    const float* pe  = (const float*)d_in[2];
    const float* nu  = (const float*)d_in[3];
    const float* th  = (const float*)d_in[4];
    const float* Bre = (const float*)d_in[5];
    const float* Bim = (const float*)d_in[6];
    const float* Cre = (const float*)d_in[7];
    const float* Cim = (const float*)d_in[8];
    const float* Dp  = (const float*)d_in[9];
    const float* rnb = (const float*)d_in[10];
    const float* w1  = (const float*)d_in[11];
    const float* b1  = (const float*)d_in[12];
    const float* w2  = (const float*)d_in[13];
    const float* b2  = (const float*)d_in[14];
    const float* fnb = (const float*)d_in[15];
    float* out = (float*)d_out;

    float *ph, *ptre, *ptim, *py; float2* pc;
    __nv_bfloat16 *phs, *psp, *pfs, *pwbu, *pwy, *pwf1, *pwf2;
    cudaGetSymbolAddress((void**)&ph,   g_h);
    cudaGetSymbolAddress((void**)&ptre, g_tre);
    cudaGetSymbolAddress((void**)&ptim, g_tim);
    cudaGetSymbolAddress((void**)&py,   g_y);
    cudaGetSymbolAddress((void**)&pc,   g_carry);
    cudaGetSymbolAddress((void**)&phs,  g_hs);
    cudaGetSymbolAddress((void**)&psp,  g_sp);
    cudaGetSymbolAddress((void**)&pfs,  g_fs);
    cudaGetSymbolAddress((void**)&pwbu, g_wbu);
    cudaGetSymbolAddress((void**)&pwy,  g_wy);
    cudaGetSymbolAddress((void**)&pwf1, g_wf1);
    cudaGetSymbolAddress((void**)&pwf2, g_wf2);

    cudaFuncSetAttribute(mma_gemm, cudaFuncAttributeMaxDynamicSharedMemorySize, SMEM_SZ);

    // streams/events created ONCE (first call = correctness run), so the graph-capture
    // call performs zero driver allocations. Device work is identical on every call.
    static cudaStream_t sx[3];
    static cudaEvent_t ef, ej[3];
    static bool inited = false;
    if (!inited){
        for (int i = 0; i < 3; i++){
            cudaStreamCreateWithFlags(&sx[i], cudaStreamNonBlocking);
            cudaEventCreateWithFlags(&ej[i], cudaEventDisableTiming);
        }
        cudaEventCreateWithFlags(&ef, cudaEventDisableTiming);
        inited = true;
    }

    // prelude on default stream
    split_all<<<dim3(12288, LL), 256>>>(Bre, Bim, Cre, Cim, w1, w2, pwbu, pwy, pwf1, pwf2);
    embed_kernel<<<(size_t)NN*HH/4/256, 256>>>(ids, we, pe, ph, phs);
    cudaEventRecord(ef, 0);
    for (int i = 0; i < 3; i++) cudaStreamWaitEvent(sx[i], ef, 0);

    int am1[6] = {0,0,1,0,0,0}, bm1[6] = {0,1,0,0,0,0};          // 3-seg: hihi, hilo, lohi
    int am2[6] = {0,0,1,2,2,3}, bm2[6] = {0,1,0,2,3,2};          // 6-seg complex

    cudaStream_t strm[4] = {0, sx[0], sx[1], sx[2]};

    for (int l = 0; l < LL; l++) {
        const float* nul = nu + l*HH;
        const float* thl = th + l*HH;

        for (int si = 0; si < 4; si++) {
            cudaStream_t st = strm[si];
            const int nb = si * SS;              // row base per batch
            const int b0 = si;                   // batch index

            // BU: [h_hi|h_lo] x [Bre;Bim] -> tre/tim (gamma fused). M=2048, K'=3072
            GArgs a = {};
            a.A = phs; a.B = pwbu + (size_t)l*2048*2048;
            a.lda = 2048; a.ldb = 2048;
            a.k1sh = 10; a.nst = 96; a.mode = 0; a.nbase = nb;
            for (int i = 0; i < 6; i++){ a.amap[i] = am1[i]; a.bmap[i] = bm1[i]; }
            a.vec = nul; a.out0 = ptre; a.out1 = ptim;
            mma_gemm<<<dim3(16, 16), 256, SMEM_SZ, st>>>(a);

            scan_pass1<<<NCHUNK*HH/256, 256, 0, st>>>(nul, thl, ptre, ptim, pc, b0);
            scan_pass3<<<NCHUNK*HH/256, 256, 0, st>>>(nul, thl, ptre, ptim, pc, psp, b0);

            // Y: [re_hi|re_lo|im_hi|im_lo] x [Cre|-Cim] -> y. M=1024, K'=6144
            a = GArgs{};
            a.A = psp; a.B = pwy + (size_t)l*1024*4096;
            a.lda = 4096; a.ldb = 4096;
            a.k1sh = 10; a.nst = 192; a.mode = 1; a.nbase = nb;
            for (int i = 0; i < 6; i++){ a.amap[i] = am2[i]; a.bmap[i] = bm2[i]; }
            a.out0 = py;
            mma_gemm<<<dim3(8, 16), 256, SMEM_SZ, st>>>(a);

            ln_kernel<<<SS, 256, 0, st>>>(ph, py, Dp + l*HH, rnb + l*HH, ph, phs, nb);

            // FFN1: h_split x w1_split -> gelu -> g_fs. M=4096, K'=3072
            a = GArgs{};
            a.A = phs; a.B = pwf1 + (size_t)l*4096*2048;
            a.lda = 2048; a.ldb = 2048;
            a.k1sh = 10; a.nst = 96; a.mode = 2; a.nbase = nb;
            for (int i = 0; i < 6; i++){ a.amap[i] = am1[i]; a.bmap[i] = bm1[i]; }
            a.vec = b1 + l*FF; a.osplit = pfs;
            mma_gemm<<<dim3(32, 16), 256, SMEM_SZ, st>>>(a);

            // FFN2: g_fs x w2_split + bias -> y. M=1024, K'=12288
            a = GArgs{};
            a.A = pfs; a.B = pwf2 + (size_t)l*1024*8192;
            a.lda = 8192; a.ldb = 8192;
            a.k1sh = 12; a.nst = 384; a.mode = 3; a.nbase = nb;
            for (int i = 0; i < 6; i++){ a.amap[i] = am1[i]; a.bmap[i] = bm1[i]; }
            a.vec = b2 + l*HH; a.out0 = py;
            mma_gemm<<<dim3(8, 16), 256, SMEM_SZ, st>>>(a);

            float* lnout = (l == LL-1) ? out : ph;
            ln_kernel<<<SS, 256, 0, st>>>(ph, py, nullptr, fnb + l*HH, lnout, phs, nb);
        }
    }

    // join
    for (int i = 0; i < 3; i++){
        cudaEventRecord(ej[i], sx[i]);
        cudaStreamWaitEvent(0, ej[i], 0);
    }
}